// round 13
// baseline (speedup 1.0000x reference)
#include <cuda_runtime.h>

typedef unsigned long long ull;
#define ABS2 0x7FFFFFFF7FFFFFFFULL
#define NBLK 128

// ---------------- scratch (device globals; no allocations) ----------------
__device__ float g_P [8192*128];
__device__ float g_Q [8192*128];
__device__ float g_U0[8192*128];
__device__ float g_U1[4096*128];
__device__ float g_ue0[64*128];
__device__ ull   g_cand[16*512];
__device__ float g_H  [32*64*128];
__device__ float g_H2 [16*64*128];
__device__ float g_peA[32*64];
__device__ float g_ueA[32*64];
__device__ float g_peB[16*64];
__device__ float g_ueB[16*64];
__device__ int   g_subA[32*64*2];
__device__ int   g_subB[16*64*4];
__device__ ull   g_part[8];
__device__ unsigned g_done[8];
__device__ unsigned g_sync[8];

// ---------------- helpers ----------------
__device__ __forceinline__ ull pk2(float x, float y) {
    ull r; asm("mov.b64 %0, {%1,%2};" : "=l"(r) : "f"(x), "f"(y)); return r;
}
__device__ __forceinline__ void upk2(ull v, float &lo, float &hi) {
    asm("mov.b64 {%0,%1}, %2;" : "=f"(lo), "=f"(hi) : "l"(v));
}
__device__ __forceinline__ ull add2(ull a, ull b) {
    ull r; asm("add.rn.f32x2 %0, %1, %2;" : "=l"(r) : "l"(a), "l"(b)); return r;
}
__device__ __forceinline__ void fma2(ull &d, ull a, ull b) {
    asm("fma.rn.f32x2 %0, %1, %2, %0;" : "+l"(d) : "l"(a), "l"(b));
}
__device__ __forceinline__ unsigned fkey(float v) {
    unsigned b = __float_as_uint(v);
    return (b & 0x80000000u) ? ~b : (b | 0x80000000u);
}
__device__ __forceinline__ float unfkey(unsigned k) {
    unsigned b = (k & 0x80000000u) ? (k & 0x7FFFFFFFu) : ~k;
    return __uint_as_float(b);
}
__device__ __forceinline__ ull umin64(ull a, ull b) { return a < b ? a : b; }

__device__ __forceinline__ void megabar(int phase) {
    __syncthreads();
    if (threadIdx.x == 0) {
        unsigned* p = &g_sync[phase];
        asm volatile("red.release.gpu.add.u32 [%0], 1;" :: "l"(p) : "memory");
        unsigned v;
        do {
            asm volatile("ld.acquire.gpu.u32 %0, [%1];" : "=r"(v) : "l"(p) : "memory");
        } while (v < NBLK);
    }
    __syncthreads();
}

// ---------------- SGEMM: 64x128 tiles, 128 thr, 8x8/thr, A pre-duplicated -
// flat grid: 0..447 gemm tiles (P 0-127, Q 128-255, U0 256-383, U1 384-447)
//            448..511 is_target (64 blocks x 128 thr)
__global__ __launch_bounds__(128) void gemm_all(
    const float* __restrict__ pos, const float* __restrict__ neg,
    const float* __restrict__ Wp1, const float* __restrict__ Wu1,
    const int* __restrict__ pcls, const int* __restrict__ tcls,
    float* __restrict__ d_out)
{
    int bid = blockIdx.x;
    int tid = threadIdx.x;

    if (bid >= 448) {    // is_target
        int i = (bid - 448)*128 + tid;
        d_out[64 + i] = (pcls[i] == tcls[i >> 10]) ? 1.f : 0.f;
        return;
    }
    if (bid == 0) {      // reset mega sync state
        if (tid < 8)  g_sync[tid] = 0u;
        if (tid >= 8 && tid < 16) { g_part[tid-8] = ~0ull; g_done[tid-8] = 0u; }
    }

    const float* A; const float* W; float* C; int row0;
    if      (bid < 128) { A = pos; W = Wp1;           C = g_P;  row0 = bid*64; }
    else if (bid < 256) { A = pos; W = Wp1 + 256*128; C = g_Q;  row0 = (bid-128)*64; }
    else if (bid < 384) { A = pos; W = Wu1;           C = g_U0; row0 = (bid-256)*64; }
    else                { A = neg; W = Wu1 + 256*128; C = g_U1; row0 = (bid-384)*64; }

    __shared__ alignas(16) ull   sA2[2][16][66];   // A duplicated (a,a), [k][row]
    __shared__ alignas(16) float sB [2][16][132];  // [k][col]

    int tx = tid & 15, ty = tid >> 4;  // tx: 8 cols, ty: 8 rows

    int aR[2], aC[2];
    #pragma unroll
    for (int i = 0; i < 2; i++) {
        int idx = tid*2 + i;           // 0..255 float4 of A tile (64x16)
        aR[i] = idx >> 2;  aC[i] = (idx & 3) * 4;
    }
    int bR[4], bC[4];
    #pragma unroll
    for (int i = 0; i < 4; i++) {
        int idx = tid*4 + i;           // 0..511 float4 of B tile (16x128)
        bR[i] = idx >> 5;  bC[i] = (idx & 31) * 4;
    }

    float4 ra[2], rb[4];
    #pragma unroll
    for (int i = 0; i < 2; i++)
        ra[i] = *(const float4*)(A + (size_t)(row0 + aR[i])*256 + aC[i]);
    #pragma unroll
    for (int i = 0; i < 4; i++)
        rb[i] = *(const float4*)(W + (size_t)bR[i]*128 + bC[i]);

    ull acc2[8][4];
    #pragma unroll
    for (int i = 0; i < 8; i++)
        #pragma unroll
        for (int j = 0; j < 4; j++) acc2[i][j] = 0ull;

    for (int k0 = 0; k0 < 16; k0++) {
        int buf = k0 & 1;
        #pragma unroll
        for (int i = 0; i < 2; i++) {
            sA2[buf][aC[i]+0][aR[i]] = pk2(ra[i].x, ra[i].x);
            sA2[buf][aC[i]+1][aR[i]] = pk2(ra[i].y, ra[i].y);
            sA2[buf][aC[i]+2][aR[i]] = pk2(ra[i].z, ra[i].z);
            sA2[buf][aC[i]+3][aR[i]] = pk2(ra[i].w, ra[i].w);
        }
        #pragma unroll
        for (int i = 0; i < 4; i++)
            *(float4*)&sB[buf][bR[i]][bC[i]] = rb[i];
        __syncthreads();
        if (k0 < 15) {
            #pragma unroll
            for (int i = 0; i < 2; i++)
                ra[i] = *(const float4*)(A + (size_t)(row0 + aR[i])*256 + (k0+1)*16 + aC[i]);
            #pragma unroll
            for (int i = 0; i < 4; i++)
                rb[i] = *(const float4*)(W + (size_t)((k0+1)*16 + bR[i])*128 + bC[i]);
        }
        #pragma unroll
        for (int k = 0; k < 16; k++) {
            ull ap[8];
            *(ulonglong2*)&ap[0] = *(const ulonglong2*)&sA2[buf][k][ty*8    ];
            *(ulonglong2*)&ap[2] = *(const ulonglong2*)&sA2[buf][k][ty*8 + 2];
            *(ulonglong2*)&ap[4] = *(const ulonglong2*)&sA2[buf][k][ty*8 + 4];
            *(ulonglong2*)&ap[6] = *(const ulonglong2*)&sA2[buf][k][ty*8 + 6];
            ull bp[4];
            bp[0] = *(const ull*)&sB[buf][k][tx*8];
            bp[1] = *(const ull*)&sB[buf][k][tx*8 + 2];
            bp[2] = *(const ull*)&sB[buf][k][tx*8 + 4];
            bp[3] = *(const ull*)&sB[buf][k][tx*8 + 6];
            #pragma unroll
            for (int i = 0; i < 8; i++)
                #pragma unroll
                for (int j = 0; j < 4; j++) fma2(acc2[i][j], ap[i], bp[j]);
        }
        __syncthreads();
    }
    #pragma unroll
    for (int i = 0; i < 8; i++) {
        int r = row0 + ty*8 + i;
        float c[8];
        #pragma unroll
        for (int j = 0; j < 4; j++) upk2(acc2[i][j], c[2*j], c[2*j+1]);
        *(float4*)(C + (size_t)r*128 + tx*8    ) = make_float4(c[0],c[1],c[2],c[3]);
        *(float4*)(C + (size_t)r*128 + tx*8 + 4) = make_float4(c[4],c[5],c[6],c[7]);
    }
}

// ---------------- radix threshold ----------------
template<int E, int NW>
__device__ void radix_thresh(const ull (&pk)[E], int K, int* hist,
                             unsigned &T, int &rem)
{
    __shared__ int wred[8];
    __shared__ int s_bin, s_prev, s_rem;
    __shared__ unsigned s_pref;
    int tid = threadIdx.x;
    int wid = tid >> 5, lane = tid & 31;
    if (tid == 0) { s_pref = 0u; s_rem = K; }
    __syncthreads();
    #pragma unroll
    for (int pass = 0; pass < 4; pass++) {
        int shift = 24 - 8*pass;
        for (int i = tid; i < NW*256; i += blockDim.x) hist[i] = 0;
        __syncthreads();
        unsigned pmask = pass ? (0xFFFFFFFFu << (shift + 8)) : 0u;
        unsigned pref = s_pref;
        #pragma unroll
        for (int e = 0; e < E; e++) {
            unsigned k = (unsigned)(pk[e] >> 32);
            if ((k & pmask) == pref)
                atomicAdd(&hist[wid*256 + ((k >> shift) & 255)], 1);
        }
        __syncthreads();
        int tot = 0, v = 0;
        if (tid < 256) {
            #pragma unroll
            for (int w = 0; w < NW; w++) tot += hist[w*256 + tid];
            v = tot;
            #pragma unroll
            for (int d = 1; d < 32; d <<= 1) {
                int u = __shfl_up_sync(0xffffffffu, v, d);
                if (lane >= d) v += u;
            }
            if (lane == 31) wred[wid] = v;
        }
        __syncthreads();
        if (tid == 0) {
            int acc = 0;
            #pragma unroll
            for (int w = 0; w < 8; w++) { int t = wred[w]; wred[w] = acc; acc += t; }
        }
        __syncthreads();
        if (tid < 256) {
            v += wred[wid];
            int rm = s_rem;
            if (v >= rm && (v - tot) < rm) { s_bin = tid; s_prev = v - tot; }
        }
        __syncthreads();
        if (tid == 0) { s_rem -= s_prev; s_pref = pref | ((unsigned)s_bin << shift); }
        __syncthreads();
    }
    T = s_pref;
    rem = s_rem;
}

template<int E, int NW>
__device__ void collect_packed(ull (&pk)[E], int K, unsigned T, int rem, ull* cand)
{
    __shared__ ull wmin[NW];
    __shared__ ull s_minv;
    __shared__ int s_cnt;
    int tid = threadIdx.x;
    if (tid == 0) s_cnt = 0;
    __syncthreads();
    #pragma unroll
    for (int e = 0; e < E; e++) {
        if ((unsigned)(pk[e] >> 32) < T) {
            int p = atomicAdd(&s_cnt, 1);
            cand[p] = pk[e];
        }
    }
    __syncthreads();
    int base = K - rem;
    for (int r = 0; r < rem; r++) {
        ull m = ~0ull;
        #pragma unroll
        for (int e = 0; e < E; e++)
            if ((unsigned)(pk[e] >> 32) == T) m = umin64(m, pk[e]);
        #pragma unroll
        for (int o = 16; o; o >>= 1) m = umin64(m, __shfl_down_sync(0xffffffffu, m, o));
        if ((tid & 31) == 0) wmin[tid >> 5] = m;
        __syncthreads();
        if (tid == 0) {
            ull mm = ~0ull;
            #pragma unroll
            for (int w = 0; w < NW; w++) mm = umin64(mm, wmin[w]);
            s_minv = mm;
            cand[base + r] = mm;
        }
        __syncthreads();
        ull mm = s_minv;
        #pragma unroll
        for (int e = 0; e < E; e++)
            if (pk[e] == mm) pk[e] = ~0ull;
    }
    __syncthreads();
}

// ---------------- persistent tail kernel (1024 threads) -------------------
__global__ __launch_bounds__(1024) void mega_kernel(
    const float* __restrict__ bp1, const float* __restrict__ Wp2,
    const float* __restrict__ bp2, const float* __restrict__ bu1,
    const float* __restrict__ Wu2, const float* __restrict__ bu2,
    float* __restrict__ d_out)
{
    extern __shared__ char smraw[];
    ull* smu = (ull*)smraw;
    int tid = threadIdx.x, bid = blockIdx.x;

    ull* sU1p  = smu;                    // 4160
    ull* sH0p  = smu + 4160;             // 64 x 33
    ull* sH1p  = sH0p + 2112;            // 64 x 129
    ull* sw2h  = sH1p + 8256;            // 64
    ull* candB = sw2h + 64;              // 64
    float* sb0B = (float*)(candB + 64);  // 32
    float* sb1B = sb0B + 32;             // 128
    int* histB  = (int*)(sb1B + 128);    // 32*256

    int bnB = bid >> 2, quadB = bid & 3, m0offB = quadB * 32;

    // ===== Phase A: unary energies =====
    {
        __shared__ float redbuf[32];
        int b = bid >> 1;
        int mbase = (bid & 1) * 64;
        int hp = tid & 63, ms = tid >> 6;
        for (int i = tid; i < 64*64; i += 1024) {
            int n = i >> 6, p = i & 63;
            float2 v = *(const float2*)(g_U1 + (size_t)b*64*128 + n*128 + 2*p);
            sU1p[p*65 + n] = pk2(v.x + bu1[2*p], v.y + bu1[2*p+1]);
        }
        float w0 = Wu2[2*hp], w1 = Wu2[2*hp+1];
        float b2u = bu2[0];
        __syncthreads();
        for (int it = 0; it < 4; it++) {
            int m = mbase + it*16 + ms;
            float2 u0 = *(const float2*)(g_U0 + ((size_t)b*128 + m)*128 + 2*hp);
            ull up = pk2(u0.x, u0.y);
            ull acc = 0ull;
            #pragma unroll 8
            for (int n = 0; n < 64; n++) {
                ull s = add2(up, sU1p[hp*65 + n]);
                acc = add2(acc, add2(s, s & ABS2));
            }
            float lo, hi; upk2(acc, lo, hi);
            float v = lo*w0 + hi*w1;
            #pragma unroll
            for (int off = 16; off; off >>= 1) v += __shfl_down_sync(0xffffffffu, v, off);
            if ((tid & 31) == 0) redbuf[tid >> 5] = v;
            __syncthreads();
            if (hp == 0) g_ue0[b*128 + m] = (redbuf[2*ms] + redbuf[2*ms+1]) * (0.5f/64.f) + b2u;
            __syncthreads();
        }
    }

    // ===== preload phase-B tiles =====
    {
        const float* h0 = g_P + (size_t)(2*bnB  )*128*128 + (size_t)m0offB*128;
        const float* h1 = g_Q + (size_t)(2*bnB+1)*128*128;
        for (int i = tid; i < 32*64; i += 1024) {
            int m = i >> 6, hp = i & 63;
            float2 v = *(const float2*)(h0 + m*128 + 2*hp);
            sH0p[hp*33 + m] = pk2(v.x, v.y);
        }
        for (int i = tid; i < 128*64; i += 1024) {
            int m = i >> 6, hp = i & 63;
            float2 v = *(const float2*)(h1 + m*128 + 2*hp);
            sH1p[hp*129 + m] = pk2(v.x + bp1[2*hp], v.y + bp1[2*hp+1]);
        }
        if (tid < 64) sw2h[tid] = pk2(0.5f*Wp2[2*tid], 0.5f*Wp2[2*tid+1]);
    }
    megabar(0);

    // ===== Phase B: level-0 quadrant scores + top-64 =====
    {
        float b2 = bp2[0];
        if (tid >= 64 && tid < 96)   sb0B[tid-64] = g_ue0[(2*bnB)*128 + m0offB + tid-64] - b2;
        if (tid >= 128 && tid < 256) sb1B[tid-128] = g_ue0[(2*bnB+1)*128 + tid-128];
        __syncthreads();

        int i0 = tid >> 7, jl = tid & 127;
        ull acc[4];
        #pragma unroll
        for (int c = 0; c < 4; c++) acc[c] = 0ull;
        for (int hp = 0; hp < 64; hp++) {
            ull wp = sw2h[hp];
            ull B = sH1p[hp*129 + jl];
            #pragma unroll
            for (int c = 0; c < 4; c++) {
                ull s = add2(sH0p[hp*33 + i0 + 8*c], B);
                s = add2(s, s & ABS2);
                fma2(acc[c], s, wp);
            }
        }
        ull pk[4];
        #pragma unroll
        for (int c = 0; c < 4; c++) {
            float lo, hi; upk2(acc[c], lo, hi);
            int m0 = i0 + 8*c;
            float val = sb0B[m0] + sb1B[jl] - (lo + hi);
            int gidx = (m0offB + m0) * 128 + jl;
            pk[c] = ((ull)fkey(val) << 32) | (unsigned)gidx;
        }
        unsigned T; int rem;
        radix_thresh<4,32>(pk, 64, histB, T, rem);
        collect_packed<4,32>(pk, 64, T, rem, candB);
        if (tid < 64) g_cand[(bnB*4 + quadB)*64 + tid] = candB[tid];
    }
    megabar(1);

    // ===== Phase C+D: level-0 merge (x4 redundant) + H gather =====
    {
        int bn = bid >> 2;
        ull*   scand = smu;                // 256
        int*   s_m0  = (int*)(scand + 256);// 64
        int*   s_m1  = s_m0 + 64;          // 64
        float* s_v   = (float*)(s_m1 + 64);// 64
        if (tid < 256) scand[tid] = g_cand[bn*256 + tid];
        __syncthreads();
        if (tid < 256) {
            ull c = scand[tid]; int rank = 0;
            #pragma unroll 16
            for (int i = 0; i < 256; i++) rank += (scand[i] < c) ? 1 : 0;
            if (rank < 64) {
                int j = (int)(c & 0xFFFFFFFFu);
                s_m0[rank] = j >> 7; s_m1[rank] = j & 127;
                s_v[rank] = unfkey((unsigned)(c >> 32));
            }
        }
        __syncthreads();
        if (tid < 64) {
            int m0 = s_m0[tid], m1 = s_m1[tid];
            float uen = g_ue0[(2*bn)*128 + m0] + g_ue0[(2*bn+1)*128 + m1];
            g_ueA[bn*64 + tid] = uen;
            g_peA[bn*64 + tid] = s_v[tid] - uen;
            g_subA[(bn*64 + tid)*2    ] = m0;
            g_subA[(bn*64 + tid)*2 + 1] = m1;
        }
        __syncthreads();
        if (tid < 512) {
            int r = (bid & 3)*16 + (tid >> 5), q = tid & 31;
            const float4* X = (const float4*)((bn & 1) ? g_Q : g_P);
            float4 a = X[((size_t)(bn*2    )*128 + s_m0[r])*32 + q];
            float4 b = X[((size_t)(bn*2 + 1)*128 + s_m1[r])*32 + q];
            ((float4*)g_H)[((size_t)bn*64 + r)*32 + q] =
                make_float4((a.x+b.x)*0.5f, (a.y+b.y)*0.5f, (a.z+b.z)*0.5f, (a.w+b.w)*0.5f);
        }
    }
    megabar(2);

    // ===== Phase E: level-1 strip scores + strip top-64 (128 blocks) =====
    {
        int bn = bid >> 3, st = bid & 7, m0off = st * 8;
        ull* sH0pE  = smu;                 // 64 x 9
        ull* sH1pE  = sH0pE + 64*9;        // 64 x 65
        ull* sw2hE  = sH1pE + 64*65;       // 64
        ull* svals  = sw2hE + 64;          // 512
        float* sb0 = (float*)(svals + 512); // 8
        float* sb1 = sb0 + 8;               // 64

        const float* h0 = g_H + (size_t)(2*bn  )*64*128 + (size_t)m0off*128;
        const float* h1 = g_H + (size_t)(2*bn+1)*64*128;
        if (tid < 512) {
            int m = tid >> 6, hp = tid & 63;
            float2 v = *(const float2*)(h0 + m*128 + 2*hp);
            sH0pE[hp*9 + m] = pk2(v.x, v.y);
        }
        for (int i = tid; i < 64*64; i += 1024) {
            int m = i >> 6, hp = i & 63;
            float2 v = *(const float2*)(h1 + m*128 + 2*hp);
            sH1pE[hp*65 + m] = pk2(v.x + bp1[2*hp], v.y + bp1[2*hp+1]);
        }
        if (tid < 64) sw2hE[tid] = pk2(0.5f*Wp2[2*tid], 0.5f*Wp2[2*tid+1]);
        float b2 = bp2[0];
        if (tid >= 64 && tid < 72)
            sb0[tid-64] = g_ueA[(2*bn)*64 + m0off + tid-64]
                        + g_peA[(2*bn)*64 + m0off + tid-64] - b2;
        if (tid >= 128 && tid < 192) {
            int m = tid - 128;
            sb1[m] = g_ueA[(2*bn+1)*64 + m] + g_peA[(2*bn+1)*64 + m];
        }
        __syncthreads();

        if (tid < 512) {
            int m0l = tid >> 6, m1 = tid & 63;
            ull acc = 0ull;
            for (int hp = 0; hp < 64; hp++) {
                ull s = add2(sH0pE[hp*9 + m0l], sH1pE[hp*65 + m1]);
                s = add2(s, s & ABS2);
                fma2(acc, s, sw2hE[hp]);
            }
            float lo, hi; upk2(acc, lo, hi);
            float val = sb0[m0l] + sb1[m1] - (lo + hi);
            int gidx = (m0off + m0l) * 64 + m1;
            svals[tid] = ((ull)fkey(val) << 32) | (unsigned)gidx;
        }
        __syncthreads();
        if (tid < 512) {
            ull c = svals[tid];
            int rank = 0;
            #pragma unroll 16
            for (int i = 0; i < 512; i++) rank += (svals[i] < c) ? 1 : 0;
            if (rank < 64) g_cand[bn*512 + st*64 + rank] = c;
        }
    }
    megabar(3);

    // ===== Phase F+G: level-1 merge (x8 redundant) + H2 gather =====
    {
        int bn = bid >> 3;
        ull*   scand = smu;                 // 512
        int*   s_m0  = (int*)(scand + 512); // 64
        int*   s_m1  = s_m0 + 64;           // 64
        float* s_v   = (float*)(s_m1 + 64); // 64
        int*   s_sub = (int*)(s_v + 64);    // 256
        if (tid < 512) scand[tid] = g_cand[bn*512 + tid];
        __syncthreads();
        if (tid < 512) {
            ull c = scand[tid]; int rank = 0;
            #pragma unroll 16
            for (int i = 0; i < 512; i++) rank += (scand[i] < c) ? 1 : 0;
            if (rank < 64) {
                int j = (int)(c & 0xFFFFFFFFu);
                s_m0[rank] = j >> 6; s_m1[rank] = j & 63;
                s_v[rank] = unfkey((unsigned)(c >> 32));
            }
        }
        __syncthreads();
        if (tid < 64) {
            int m0 = s_m0[tid], m1 = s_m1[tid];
            float uen = g_ueA[(2*bn)*64 + m0] + g_ueA[(2*bn+1)*64 + m1];
            g_ueB[bn*64 + tid] = uen;
            g_peB[bn*64 + tid] = s_v[tid] - uen;
            int a0 = g_subA[((2*bn)*64 + m0)*2], a1 = g_subA[((2*bn)*64 + m0)*2 + 1];
            int b0 = g_subA[((2*bn+1)*64 + m1)*2], b1 = g_subA[((2*bn+1)*64 + m1)*2 + 1];
            s_sub[tid*4+0] = a0; s_sub[tid*4+1] = a1;
            s_sub[tid*4+2] = b0; s_sub[tid*4+3] = b1;
            g_subB[(bn*64 + tid)*4 + 0] = a0;
            g_subB[(bn*64 + tid)*4 + 1] = a1;
            g_subB[(bn*64 + tid)*4 + 2] = b0;
            g_subB[(bn*64 + tid)*4 + 3] = b1;
        }
        __syncthreads();
        if (tid < 256) {
            int r = (bid & 7)*8 + (tid >> 5), q = tid & 31;
            const float4* X = (const float4*)((bn & 1) ? g_Q : g_P);
            float4 s = make_float4(0.f, 0.f, 0.f, 0.f);
            #pragma unroll
            for (int i = 0; i < 4; i++) {
                float4 v = X[((size_t)(bn*4 + i)*128 + s_sub[r*4 + i])*32 + q];
                s.x += v.x; s.y += v.y; s.z += v.z; s.w += v.w;
            }
            ((float4*)g_H2)[((size_t)bn*64 + r)*32 + q] =
                make_float4(s.x*0.25f, s.y*0.25f, s.z*0.25f, s.w*0.25f);
        }
    }
    megabar(4);

    // ===== Phase H: level-2 strip argmin + fused final (32 blocks) =====
    if (bid < 32) {
        int bn = bid >> 2, m0off = (bid & 3) * 16;
        ull* sH0pH = smu;                  // 64 x 17
        ull* sH1pH = sH0pH + 64*17;        // 64 x 65
        ull* sw2hH = sH1pH + 64*65;        // 64
        float* sb0 = (float*)(sw2hH + 64); // 16
        float* sb1 = sb0 + 16;             // 64
        __shared__ ull hw[32];

        const float* h0 = g_H2 + (size_t)(2*bn  )*64*128 + (size_t)m0off*128;
        const float* h1 = g_H2 + (size_t)(2*bn+1)*64*128;
        if (tid < 16*64) {
            int m = tid >> 6, hp = tid & 63;
            float2 v = *(const float2*)(h0 + m*128 + 2*hp);
            sH0pH[hp*17 + m] = pk2(v.x, v.y);
        }
        for (int i = tid; i < 64*64; i += 1024) {
            int m = i >> 6, hp = i & 63;
            float2 v = *(const float2*)(h1 + m*128 + 2*hp);
            sH1pH[hp*65 + m] = pk2(v.x + bp1[2*hp], v.y + bp1[2*hp+1]);
        }
        if (tid < 64) sw2hH[tid] = pk2(0.5f*Wp2[2*tid], 0.5f*Wp2[2*tid+1]);
        float b2 = bp2[0];
        if (tid >= 64 && tid < 80)
            sb0[tid-64] = g_ueB[(2*bn)*64 + m0off + tid-64]
                        + g_peB[(2*bn)*64 + m0off + tid-64] - b2;
        if (tid >= 128 && tid < 192) {
            int m = tid - 128;
            sb1[m] = g_ueB[(2*bn+1)*64 + m] + g_peB[(2*bn+1)*64 + m];
        }
        __syncthreads();

        int m0l = tid >> 6, m1 = tid & 63;
        ull acc = 0ull;
        for (int hp = 0; hp < 64; hp++) {
            ull s = add2(sH0pH[hp*17 + m0l], sH1pH[hp*65 + m1]);
            s = add2(s, s & ABS2);
            fma2(acc, s, sw2hH[hp]);
        }
        ull mbest;
        {
            float lo, hi; upk2(acc, lo, hi);
            float val = sb0[m0l] + sb1[m1] - (lo + hi);
            int gidx = (m0off + m0l) * 64 + m1;
            mbest = ((ull)fkey(val) << 32) | (unsigned)gidx;
        }
        #pragma unroll
        for (int o = 16; o; o >>= 1) mbest = umin64(mbest, __shfl_down_sync(0xffffffffu, mbest, o));
        if ((tid & 31) == 0) hw[tid >> 5] = mbest;
        __syncthreads();
        if (tid == 0) {
            ull mm = ~0ull;
            #pragma unroll
            for (int w = 0; w < 32; w++) mm = umin64(mm, hw[w]);
            asm volatile("red.global.min.u64 [%0], %1;" :: "l"(&g_part[bn]), "l"(mm) : "memory");
            unsigned old;
            asm volatile("atom.acq_rel.gpu.global.add.u32 %0, [%1], %2;"
                         : "=r"(old) : "l"(&g_done[bn]), "r"(1u) : "memory");
            if (old == 3u) {
                ull fin;
                asm volatile("ld.acquire.gpu.global.u64 %0, [%1];"
                             : "=l"(fin) : "l"(&g_part[bn]) : "memory");
                int j = (int)(fin & 0xFFFFFFFFu);
                int m0 = j >> 6, m1w = j & 63;
                #pragma unroll
                for (int s = 0; s < 4; s++) {
                    d_out[bn*8 + s]     = (float)g_subB[((2*bn)*64 + m0)*4 + s];
                    d_out[bn*8 + 4 + s] = (float)g_subB[((2*bn+1)*64 + m1w)*4 + s];
                }
            }
        }
    }
}

// ---------------- launch ----------------
extern "C" void kernel_launch(void* const* d_in, const int* in_sizes, int n_in,
                              void* d_out, int out_size)
{
    const float* pos  = (const float*)d_in[0];
    const float* neg  = (const float*)d_in[1];
    const int*   pcls = (const int*)  d_in[2];
    const int*   tcls = (const int*)  d_in[3];
    const float* Wp1  = (const float*)d_in[4];
    const float* bp1  = (const float*)d_in[5];
    const float* Wp2  = (const float*)d_in[6];
    const float* bp2  = (const float*)d_in[7];
    const float* Wu1  = (const float*)d_in[8];
    const float* bu1  = (const float*)d_in[9];
    const float* Wu2  = (const float*)d_in[10];
    const float* bu2  = (const float*)d_in[11];
    float* out = (float*)d_out;

    // dynamic smem: 14656 ull + 160 f + 32*256 int = 150,656 B
    size_t smM = (size_t)14656*8 + 160*4 + (size_t)32*256*4;

    cudaFuncSetAttribute(mega_kernel, cudaFuncAttributeMaxDynamicSharedMemorySize, (int)smM);

    gemm_all<<<512, 128>>>(pos, neg, Wp1, Wu1, pcls, tcls, out);
    mega_kernel<<<NBLK, 1024, smM>>>(bp1, Wp2, bp2, bu1, Wu2, bu2, out);
}

// round 14
// speedup vs baseline: 1.0600x; 1.0600x over previous
#include <cuda_runtime.h>

typedef unsigned long long ull;
#define ABS2 0x7FFFFFFF7FFFFFFFULL
#define NBLK 128

// ---------------- scratch (device globals; no allocations) ----------------
__device__ float g_P [8192*128];
__device__ float g_Q [8192*128];
__device__ float g_U0[8192*128];
__device__ float g_U1[4096*128];
__device__ float g_ue0[64*128];
__device__ ull   g_cand[16*512];
__device__ float g_H  [32*64*128];
__device__ float g_H2 [16*64*128];
__device__ float g_peA[32*64];
__device__ float g_ueA[32*64];
__device__ float g_peB[16*64];
__device__ float g_ueB[16*64];
__device__ int   g_subA[32*64*2];
__device__ int   g_subB[16*64*4];
__device__ ull   g_part[8];
__device__ unsigned g_done[8];
__device__ unsigned g_sync[8];

// ---------------- helpers ----------------
__device__ __forceinline__ ull pk2(float x, float y) {
    ull r; asm("mov.b64 %0, {%1,%2};" : "=l"(r) : "f"(x), "f"(y)); return r;
}
__device__ __forceinline__ void upk2(ull v, float &lo, float &hi) {
    asm("mov.b64 {%0,%1}, %2;" : "=f"(lo), "=f"(hi) : "l"(v));
}
__device__ __forceinline__ ull add2(ull a, ull b) {
    ull r; asm("add.rn.f32x2 %0, %1, %2;" : "=l"(r) : "l"(a), "l"(b)); return r;
}
__device__ __forceinline__ void fma2(ull &d, ull a, ull b) {
    asm("fma.rn.f32x2 %0, %1, %2, %0;" : "+l"(d) : "l"(a), "l"(b));
}
__device__ __forceinline__ unsigned fkey(float v) {
    unsigned b = __float_as_uint(v);
    return (b & 0x80000000u) ? ~b : (b | 0x80000000u);
}
__device__ __forceinline__ float unfkey(unsigned k) {
    unsigned b = (k & 0x80000000u) ? (k & 0x7FFFFFFFu) : ~k;
    return __uint_as_float(b);
}
__device__ __forceinline__ ull umin64(ull a, ull b) { return a < b ? a : b; }

__device__ __forceinline__ void megabar(int phase) {
    __syncthreads();
    if (threadIdx.x == 0) {
        unsigned* p = &g_sync[phase];
        asm volatile("red.release.gpu.add.u32 [%0], 1;" :: "l"(p) : "memory");
        unsigned v;
        do {
            asm volatile("ld.acquire.gpu.u32 %0, [%1];" : "=r"(v) : "l"(p) : "memory");
        } while (v < NBLK);
    }
    __syncthreads();
}

// ---------------- SGEMM: 64x128 tiles, 128 thr, 8x8/thr, B pair-major -----
// flat grid: 0..447 gemm tiles (P 0-127, Q 128-255, U0 256-383, U1 384-447)
//            448..511 is_target (64 blocks x 128 thr)
__global__ __launch_bounds__(128) void gemm_all(
    const float* __restrict__ pos, const float* __restrict__ neg,
    const float* __restrict__ Wp1, const float* __restrict__ Wu1,
    const int* __restrict__ pcls, const int* __restrict__ tcls,
    float* __restrict__ d_out)
{
    int bid = blockIdx.x;
    int tid = threadIdx.x;

    if (bid >= 448) {    // is_target
        int i = (bid - 448)*128 + tid;
        d_out[64 + i] = (pcls[i] == tcls[i >> 10]) ? 1.f : 0.f;
        return;
    }
    if (bid == 0) {      // reset mega sync state
        if (tid < 8)  g_sync[tid] = 0u;
        if (tid >= 8 && tid < 16) { g_part[tid-8] = ~0ull; g_done[tid-8] = 0u; }
    }

    const float* A; const float* W; float* C; int row0;
    if      (bid < 128) { A = pos; W = Wp1;           C = g_P;  row0 = bid*64; }
    else if (bid < 256) { A = pos; W = Wp1 + 256*128; C = g_Q;  row0 = (bid-128)*64; }
    else if (bid < 384) { A = pos; W = Wu1;           C = g_U0; row0 = (bid-256)*64; }
    else                { A = neg; W = Wu1 + 256*128; C = g_U1; row0 = (bid-384)*64; }

    __shared__ alignas(16) float sA [2][16][68];      // [k][row] transposed
    __shared__ alignas(16) ull   sBt[2][16][4][17];   // [k][pair%4][pair/4] col-pairs

    int tx = tid & 15, ty = tid >> 4;  // tx: 8 cols, ty: 8 rows

    int aR[2], aC[2];
    #pragma unroll
    for (int i = 0; i < 2; i++) {
        int idx = tid*2 + i;           // 0..255 float4 of A tile (64x16)
        aR[i] = idx >> 2;  aC[i] = (idx & 3) * 4;
    }
    int bR[4], bP0[4];                 // row, first col-pair index (even)
    #pragma unroll
    for (int i = 0; i < 4; i++) {
        int idx = tid*4 + i;           // 0..511 float4 of B tile (16x128)
        bR[i]  = idx >> 5;
        bP0[i] = (idx & 31) * 2;       // pair index = col/2
    }

    float4 ra[2], rb[4];
    #pragma unroll
    for (int i = 0; i < 2; i++)
        ra[i] = *(const float4*)(A + (size_t)(row0 + aR[i])*256 + aC[i]);
    #pragma unroll
    for (int i = 0; i < 4; i++)
        rb[i] = *(const float4*)(W + (size_t)bR[i]*128 + bP0[i]*2);

    ull acc2[8][4];
    #pragma unroll
    for (int i = 0; i < 8; i++)
        #pragma unroll
        for (int j = 0; j < 4; j++) acc2[i][j] = 0ull;

    for (int k0 = 0; k0 < 16; k0++) {
        int buf = k0 & 1;
        #pragma unroll
        for (int i = 0; i < 2; i++) {
            sA[buf][aC[i]+0][aR[i]] = ra[i].x;
            sA[buf][aC[i]+1][aR[i]] = ra[i].y;
            sA[buf][aC[i]+2][aR[i]] = ra[i].z;
            sA[buf][aC[i]+3][aR[i]] = ra[i].w;
        }
        #pragma unroll
        for (int i = 0; i < 4; i++) {
            int p0 = bP0[i], p1 = bP0[i] + 1;
            sBt[buf][bR[i]][p0 & 3][p0 >> 2] = pk2(rb[i].x, rb[i].y);
            sBt[buf][bR[i]][p1 & 3][p1 >> 2] = pk2(rb[i].z, rb[i].w);
        }
        __syncthreads();
        if (k0 < 15) {
            #pragma unroll
            for (int i = 0; i < 2; i++)
                ra[i] = *(const float4*)(A + (size_t)(row0 + aR[i])*256 + (k0+1)*16 + aC[i]);
            #pragma unroll
            for (int i = 0; i < 4; i++)
                rb[i] = *(const float4*)(W + (size_t)((k0+1)*16 + bR[i])*128 + bP0[i]*2);
        }
        #pragma unroll
        for (int k = 0; k < 16; k++) {
            float4 a0 = *(const float4*)&sA[buf][k][ty*8];
            float4 a1 = *(const float4*)&sA[buf][k][ty*8 + 4];
            ull bp[4];
            #pragma unroll
            for (int j = 0; j < 4; j++) bp[j] = sBt[buf][k][j][tx];  // conflict-free
            float av[8] = {a0.x, a0.y, a0.z, a0.w, a1.x, a1.y, a1.z, a1.w};
            #pragma unroll
            for (int i = 0; i < 8; i++) {
                ull ap = pk2(av[i], av[i]);
                #pragma unroll
                for (int j = 0; j < 4; j++) fma2(acc2[i][j], ap, bp[j]);
            }
        }
        __syncthreads();
    }
    #pragma unroll
    for (int i = 0; i < 8; i++) {
        int r = row0 + ty*8 + i;
        float c[8];
        #pragma unroll
        for (int j = 0; j < 4; j++) upk2(acc2[i][j], c[2*j], c[2*j+1]);
        *(float4*)(C + (size_t)r*128 + tx*8    ) = make_float4(c[0],c[1],c[2],c[3]);
        *(float4*)(C + (size_t)r*128 + tx*8 + 4) = make_float4(c[4],c[5],c[6],c[7]);
    }
}

// ---------------- radix threshold ----------------
template<int E, int NW>
__device__ void radix_thresh(const ull (&pk)[E], int K, int* hist,
                             unsigned &T, int &rem)
{
    __shared__ int wred[8];
    __shared__ int s_bin, s_prev, s_rem;
    __shared__ unsigned s_pref;
    int tid = threadIdx.x;
    int wid = tid >> 5, lane = tid & 31;
    if (tid == 0) { s_pref = 0u; s_rem = K; }
    __syncthreads();
    #pragma unroll
    for (int pass = 0; pass < 4; pass++) {
        int shift = 24 - 8*pass;
        for (int i = tid; i < NW*256; i += blockDim.x) hist[i] = 0;
        __syncthreads();
        unsigned pmask = pass ? (0xFFFFFFFFu << (shift + 8)) : 0u;
        unsigned pref = s_pref;
        #pragma unroll
        for (int e = 0; e < E; e++) {
            unsigned k = (unsigned)(pk[e] >> 32);
            if ((k & pmask) == pref)
                atomicAdd(&hist[wid*256 + ((k >> shift) & 255)], 1);
        }
        __syncthreads();
        int tot = 0, v = 0;
        if (tid < 256) {
            #pragma unroll
            for (int w = 0; w < NW; w++) tot += hist[w*256 + tid];
            v = tot;
            #pragma unroll
            for (int d = 1; d < 32; d <<= 1) {
                int u = __shfl_up_sync(0xffffffffu, v, d);
                if (lane >= d) v += u;
            }
            if (lane == 31) wred[wid] = v;
        }
        __syncthreads();
        if (tid == 0) {
            int acc = 0;
            #pragma unroll
            for (int w = 0; w < 8; w++) { int t = wred[w]; wred[w] = acc; acc += t; }
        }
        __syncthreads();
        if (tid < 256) {
            v += wred[wid];
            int rm = s_rem;
            if (v >= rm && (v - tot) < rm) { s_bin = tid; s_prev = v - tot; }
        }
        __syncthreads();
        if (tid == 0) { s_rem -= s_prev; s_pref = pref | ((unsigned)s_bin << shift); }
        __syncthreads();
    }
    T = s_pref;
    rem = s_rem;
}

template<int E, int NW>
__device__ void collect_packed(ull (&pk)[E], int K, unsigned T, int rem, ull* cand)
{
    __shared__ ull wmin[NW];
    __shared__ ull s_minv;
    __shared__ int s_cnt;
    int tid = threadIdx.x;
    if (tid == 0) s_cnt = 0;
    __syncthreads();
    #pragma unroll
    for (int e = 0; e < E; e++) {
        if ((unsigned)(pk[e] >> 32) < T) {
            int p = atomicAdd(&s_cnt, 1);
            cand[p] = pk[e];
        }
    }
    __syncthreads();
    int base = K - rem;
    for (int r = 0; r < rem; r++) {
        ull m = ~0ull;
        #pragma unroll
        for (int e = 0; e < E; e++)
            if ((unsigned)(pk[e] >> 32) == T) m = umin64(m, pk[e]);
        #pragma unroll
        for (int o = 16; o; o >>= 1) m = umin64(m, __shfl_down_sync(0xffffffffu, m, o));
        if ((tid & 31) == 0) wmin[tid >> 5] = m;
        __syncthreads();
        if (tid == 0) {
            ull mm = ~0ull;
            #pragma unroll
            for (int w = 0; w < NW; w++) mm = umin64(mm, wmin[w]);
            s_minv = mm;
            cand[base + r] = mm;
        }
        __syncthreads();
        ull mm = s_minv;
        #pragma unroll
        for (int e = 0; e < E; e++)
            if (pk[e] == mm) pk[e] = ~0ull;
    }
    __syncthreads();
}

// ---------------- persistent tail kernel (1024 threads) -------------------
__global__ __launch_bounds__(1024) void mega_kernel(
    const float* __restrict__ bp1, const float* __restrict__ Wp2,
    const float* __restrict__ bp2, const float* __restrict__ bu1,
    const float* __restrict__ Wu2, const float* __restrict__ bu2,
    float* __restrict__ d_out)
{
    extern __shared__ char smraw[];
    ull* smu = (ull*)smraw;
    int tid = threadIdx.x, bid = blockIdx.x;

    ull* sU1p  = smu;                    // 4160
    ull* sH0p  = smu + 4160;             // 64 x 33
    ull* sH1p  = sH0p + 2112;            // 64 x 129
    ull* sw2h  = sH1p + 8256;            // 64
    ull* candB = sw2h + 64;              // 64
    float* sb0B = (float*)(candB + 64);  // 32
    float* sb1B = sb0B + 32;             // 128
    int* histB  = (int*)(sb1B + 128);    // 32*256

    int bnB = bid >> 2, quadB = bid & 3, m0offB = quadB * 32;

    // ===== Phase A: unary energies =====
    {
        __shared__ float redbuf[32];
        int b = bid >> 1;
        int mbase = (bid & 1) * 64;
        int hp = tid & 63, ms = tid >> 6;
        for (int i = tid; i < 64*64; i += 1024) {
            int n = i >> 6, p = i & 63;
            float2 v = *(const float2*)(g_U1 + (size_t)b*64*128 + n*128 + 2*p);
            sU1p[p*65 + n] = pk2(v.x + bu1[2*p], v.y + bu1[2*p+1]);
        }
        float w0 = Wu2[2*hp], w1 = Wu2[2*hp+1];
        float b2u = bu2[0];
        __syncthreads();
        for (int it = 0; it < 4; it++) {
            int m = mbase + it*16 + ms;
            float2 u0 = *(const float2*)(g_U0 + ((size_t)b*128 + m)*128 + 2*hp);
            ull up = pk2(u0.x, u0.y);
            ull acc = 0ull;
            #pragma unroll 8
            for (int n = 0; n < 64; n++) {
                ull s = add2(up, sU1p[hp*65 + n]);
                acc = add2(acc, add2(s, s & ABS2));
            }
            float lo, hi; upk2(acc, lo, hi);
            float v = lo*w0 + hi*w1;
            #pragma unroll
            for (int off = 16; off; off >>= 1) v += __shfl_down_sync(0xffffffffu, v, off);
            if ((tid & 31) == 0) redbuf[tid >> 5] = v;
            __syncthreads();
            if (hp == 0) g_ue0[b*128 + m] = (redbuf[2*ms] + redbuf[2*ms+1]) * (0.5f/64.f) + b2u;
            __syncthreads();
        }
    }

    // ===== preload phase-B tiles =====
    {
        const float* h0 = g_P + (size_t)(2*bnB  )*128*128 + (size_t)m0offB*128;
        const float* h1 = g_Q + (size_t)(2*bnB+1)*128*128;
        for (int i = tid; i < 32*64; i += 1024) {
            int m = i >> 6, hp = i & 63;
            float2 v = *(const float2*)(h0 + m*128 + 2*hp);
            sH0p[hp*33 + m] = pk2(v.x, v.y);
        }
        for (int i = tid; i < 128*64; i += 1024) {
            int m = i >> 6, hp = i & 63;
            float2 v = *(const float2*)(h1 + m*128 + 2*hp);
            sH1p[hp*129 + m] = pk2(v.x + bp1[2*hp], v.y + bp1[2*hp+1]);
        }
        if (tid < 64) sw2h[tid] = pk2(0.5f*Wp2[2*tid], 0.5f*Wp2[2*tid+1]);
    }
    megabar(0);

    // ===== Phase B: level-0 quadrant scores + top-64 =====
    {
        float b2 = bp2[0];
        if (tid >= 64 && tid < 96)   sb0B[tid-64] = g_ue0[(2*bnB)*128 + m0offB + tid-64] - b2;
        if (tid >= 128 && tid < 256) sb1B[tid-128] = g_ue0[(2*bnB+1)*128 + tid-128];
        __syncthreads();

        int i0 = tid >> 7, jl = tid & 127;
        ull acc[4];
        #pragma unroll
        for (int c = 0; c < 4; c++) acc[c] = 0ull;
        for (int hp = 0; hp < 64; hp++) {
            ull wp = sw2h[hp];
            ull B = sH1p[hp*129 + jl];
            #pragma unroll
            for (int c = 0; c < 4; c++) {
                ull s = add2(sH0p[hp*33 + i0 + 8*c], B);
                s = add2(s, s & ABS2);
                fma2(acc[c], s, wp);
            }
        }
        ull pk[4];
        #pragma unroll
        for (int c = 0; c < 4; c++) {
            float lo, hi; upk2(acc[c], lo, hi);
            int m0 = i0 + 8*c;
            float val = sb0B[m0] + sb1B[jl] - (lo + hi);
            int gidx = (m0offB + m0) * 128 + jl;
            pk[c] = ((ull)fkey(val) << 32) | (unsigned)gidx;
        }
        unsigned T; int rem;
        radix_thresh<4,32>(pk, 64, histB, T, rem);
        collect_packed<4,32>(pk, 64, T, rem, candB);
        if (tid < 64) g_cand[(bnB*4 + quadB)*64 + tid] = candB[tid];
    }
    megabar(1);

    // ===== Phase C+D: level-0 merge (x4 redundant) + H gather =====
    {
        int bn = bid >> 2;
        ull*   scand = smu;                // 256
        int*   s_m0  = (int*)(scand + 256);// 64
        int*   s_m1  = s_m0 + 64;          // 64
        float* s_v   = (float*)(s_m1 + 64);// 64
        if (tid < 256) scand[tid] = g_cand[bn*256 + tid];
        __syncthreads();
        if (tid < 256) {
            ull c = scand[tid]; int rank = 0;
            #pragma unroll 16
            for (int i = 0; i < 256; i++) rank += (scand[i] < c) ? 1 : 0;
            if (rank < 64) {
                int j = (int)(c & 0xFFFFFFFFu);
                s_m0[rank] = j >> 7; s_m1[rank] = j & 127;
                s_v[rank] = unfkey((unsigned)(c >> 32));
            }
        }
        __syncthreads();
        if (tid < 64) {
            int m0 = s_m0[tid], m1 = s_m1[tid];
            float uen = g_ue0[(2*bn)*128 + m0] + g_ue0[(2*bn+1)*128 + m1];
            g_ueA[bn*64 + tid] = uen;
            g_peA[bn*64 + tid] = s_v[tid] - uen;
            g_subA[(bn*64 + tid)*2    ] = m0;
            g_subA[(bn*64 + tid)*2 + 1] = m1;
        }
        __syncthreads();
        if (tid < 512) {
            int r = (bid & 3)*16 + (tid >> 5), q = tid & 31;
            const float4* X = (const float4*)((bn & 1) ? g_Q : g_P);
            float4 a = X[((size_t)(bn*2    )*128 + s_m0[r])*32 + q];
            float4 b = X[((size_t)(bn*2 + 1)*128 + s_m1[r])*32 + q];
            ((float4*)g_H)[((size_t)bn*64 + r)*32 + q] =
                make_float4((a.x+b.x)*0.5f, (a.y+b.y)*0.5f, (a.z+b.z)*0.5f, (a.w+b.w)*0.5f);
        }
    }
    megabar(2);

    // ===== Phase E: level-1 strip scores + strip top-64 (128 blocks) =====
    {
        int bn = bid >> 3, st = bid & 7, m0off = st * 8;
        ull* sH0pE  = smu;                 // 64 x 9
        ull* sH1pE  = sH0pE + 64*9;        // 64 x 65
        ull* sw2hE  = sH1pE + 64*65;       // 64
        ull* svals  = sw2hE + 64;          // 512
        float* sb0 = (float*)(svals + 512); // 8
        float* sb1 = sb0 + 8;               // 64

        const float* h0 = g_H + (size_t)(2*bn  )*64*128 + (size_t)m0off*128;
        const float* h1 = g_H + (size_t)(2*bn+1)*64*128;
        if (tid < 512) {
            int m = tid >> 6, hp = tid & 63;
            float2 v = *(const float2*)(h0 + m*128 + 2*hp);
            sH0pE[hp*9 + m] = pk2(v.x, v.y);
        }
        for (int i = tid; i < 64*64; i += 1024) {
            int m = i >> 6, hp = i & 63;
            float2 v = *(const float2*)(h1 + m*128 + 2*hp);
            sH1pE[hp*65 + m] = pk2(v.x + bp1[2*hp], v.y + bp1[2*hp+1]);
        }
        if (tid < 64) sw2hE[tid] = pk2(0.5f*Wp2[2*tid], 0.5f*Wp2[2*tid+1]);
        float b2 = bp2[0];
        if (tid >= 64 && tid < 72)
            sb0[tid-64] = g_ueA[(2*bn)*64 + m0off + tid-64]
                        + g_peA[(2*bn)*64 + m0off + tid-64] - b2;
        if (tid >= 128 && tid < 192) {
            int m = tid - 128;
            sb1[m] = g_ueA[(2*bn+1)*64 + m] + g_peA[(2*bn+1)*64 + m];
        }
        __syncthreads();

        if (tid < 512) {
            int m0l = tid >> 6, m1 = tid & 63;
            ull acc = 0ull;
            for (int hp = 0; hp < 64; hp++) {
                ull s = add2(sH0pE[hp*9 + m0l], sH1pE[hp*65 + m1]);
                s = add2(s, s & ABS2);
                fma2(acc, s, sw2hE[hp]);
            }
            float lo, hi; upk2(acc, lo, hi);
            float val = sb0[m0l] + sb1[m1] - (lo + hi);
            int gidx = (m0off + m0l) * 64 + m1;
            svals[tid] = ((ull)fkey(val) << 32) | (unsigned)gidx;
        }
        __syncthreads();
        if (tid < 512) {
            ull c = svals[tid];
            int rank = 0;
            #pragma unroll 16
            for (int i = 0; i < 512; i++) rank += (svals[i] < c) ? 1 : 0;
            if (rank < 64) g_cand[bn*512 + st*64 + rank] = c;
        }
    }
    megabar(3);

    // ===== Phase F+G: level-1 merge (x8 redundant) + H2 gather =====
    {
        int bn = bid >> 3;
        ull*   scand = smu;                 // 512
        int*   s_m0  = (int*)(scand + 512); // 64
        int*   s_m1  = s_m0 + 64;           // 64
        float* s_v   = (float*)(s_m1 + 64); // 64
        int*   s_sub = (int*)(s_v + 64);    // 256
        if (tid < 512) scand[tid] = g_cand[bn*512 + tid];
        __syncthreads();
        if (tid < 512) {
            ull c = scand[tid]; int rank = 0;
            #pragma unroll 16
            for (int i = 0; i < 512; i++) rank += (scand[i] < c) ? 1 : 0;
            if (rank < 64) {
                int j = (int)(c & 0xFFFFFFFFu);
                s_m0[rank] = j >> 6; s_m1[rank] = j & 63;
                s_v[rank] = unfkey((unsigned)(c >> 32));
            }
        }
        __syncthreads();
        if (tid < 64) {
            int m0 = s_m0[tid], m1 = s_m1[tid];
            float uen = g_ueA[(2*bn)*64 + m0] + g_ueA[(2*bn+1)*64 + m1];
            g_ueB[bn*64 + tid] = uen;
            g_peB[bn*64 + tid] = s_v[tid] - uen;
            int a0 = g_subA[((2*bn)*64 + m0)*2], a1 = g_subA[((2*bn)*64 + m0)*2 + 1];
            int b0 = g_subA[((2*bn+1)*64 + m1)*2], b1 = g_subA[((2*bn+1)*64 + m1)*2 + 1];
            s_sub[tid*4+0] = a0; s_sub[tid*4+1] = a1;
            s_sub[tid*4+2] = b0; s_sub[tid*4+3] = b1;
            g_subB[(bn*64 + tid)*4 + 0] = a0;
            g_subB[(bn*64 + tid)*4 + 1] = a1;
            g_subB[(bn*64 + tid)*4 + 2] = b0;
            g_subB[(bn*64 + tid)*4 + 3] = b1;
        }
        __syncthreads();
        if (tid < 256) {
            int r = (bid & 7)*8 + (tid >> 5), q = tid & 31;
            const float4* X = (const float4*)((bn & 1) ? g_Q : g_P);
            float4 s = make_float4(0.f, 0.f, 0.f, 0.f);
            #pragma unroll
            for (int i = 0; i < 4; i++) {
                float4 v = X[((size_t)(bn*4 + i)*128 + s_sub[r*4 + i])*32 + q];
                s.x += v.x; s.y += v.y; s.z += v.z; s.w += v.w;
            }
            ((float4*)g_H2)[((size_t)bn*64 + r)*32 + q] =
                make_float4(s.x*0.25f, s.y*0.25f, s.z*0.25f, s.w*0.25f);
        }
    }
    megabar(4);

    // ===== Phase H: level-2 strip argmin + fused final (32 blocks) =====
    if (bid < 32) {
        int bn = bid >> 2, m0off = (bid & 3) * 16;
        ull* sH0pH = smu;                  // 64 x 17
        ull* sH1pH = sH0pH + 64*17;        // 64 x 65
        ull* sw2hH = sH1pH + 64*65;        // 64
        float* sb0 = (float*)(sw2hH + 64); // 16
        float* sb1 = sb0 + 16;             // 64
        __shared__ ull hw[32];

        const float* h0 = g_H2 + (size_t)(2*bn  )*64*128 + (size_t)m0off*128;
        const float* h1 = g_H2 + (size_t)(2*bn+1)*64*128;
        if (tid < 16*64) {
            int m = tid >> 6, hp = tid & 63;
            float2 v = *(const float2*)(h0 + m*128 + 2*hp);
            sH0pH[hp*17 + m] = pk2(v.x, v.y);
        }
        for (int i = tid; i < 64*64; i += 1024) {
            int m = i >> 6, hp = i & 63;
            float2 v = *(const float2*)(h1 + m*128 + 2*hp);
            sH1pH[hp*65 + m] = pk2(v.x + bp1[2*hp], v.y + bp1[2*hp+1]);
        }
        if (tid < 64) sw2hH[tid] = pk2(0.5f*Wp2[2*tid], 0.5f*Wp2[2*tid+1]);
        float b2 = bp2[0];
        if (tid >= 64 && tid < 80)
            sb0[tid-64] = g_ueB[(2*bn)*64 + m0off + tid-64]
                        + g_peB[(2*bn)*64 + m0off + tid-64] - b2;
        if (tid >= 128 && tid < 192) {
            int m = tid - 128;
            sb1[m] = g_ueB[(2*bn+1)*64 + m] + g_peB[(2*bn+1)*64 + m];
        }
        __syncthreads();

        int m0l = tid >> 6, m1 = tid & 63;
        ull acc = 0ull;
        for (int hp = 0; hp < 64; hp++) {
            ull s = add2(sH0pH[hp*17 + m0l], sH1pH[hp*65 + m1]);
            s = add2(s, s & ABS2);
            fma2(acc, s, sw2hH[hp]);
        }
        ull mbest;
        {
            float lo, hi; upk2(acc, lo, hi);
            float val = sb0[m0l] + sb1[m1] - (lo + hi);
            int gidx = (m0off + m0l) * 64 + m1;
            mbest = ((ull)fkey(val) << 32) | (unsigned)gidx;
        }
        #pragma unroll
        for (int o = 16; o; o >>= 1) mbest = umin64(mbest, __shfl_down_sync(0xffffffffu, mbest, o));
        if ((tid & 31) == 0) hw[tid >> 5] = mbest;
        __syncthreads();
        if (tid == 0) {
            ull mm = ~0ull;
            #pragma unroll
            for (int w = 0; w < 32; w++) mm = umin64(mm, hw[w]);
            asm volatile("red.global.min.u64 [%0], %1;" :: "l"(&g_part[bn]), "l"(mm) : "memory");
            unsigned old;
            asm volatile("atom.acq_rel.gpu.global.add.u32 %0, [%1], %2;"
                         : "=r"(old) : "l"(&g_done[bn]), "r"(1u) : "memory");
            if (old == 3u) {
                ull fin;
                asm volatile("ld.acquire.gpu.global.u64 %0, [%1];"
                             : "=l"(fin) : "l"(&g_part[bn]) : "memory");
                int j = (int)(fin & 0xFFFFFFFFu);
                int m0 = j >> 6, m1w = j & 63;
                #pragma unroll
                for (int s = 0; s < 4; s++) {
                    d_out[bn*8 + s]     = (float)g_subB[((2*bn)*64 + m0)*4 + s];
                    d_out[bn*8 + 4 + s] = (float)g_subB[((2*bn+1)*64 + m1w)*4 + s];
                }
            }
        }
    }
}

// ---------------- launch ----------------
extern "C" void kernel_launch(void* const* d_in, const int* in_sizes, int n_in,
                              void* d_out, int out_size)
{
    const float* pos  = (const float*)d_in[0];
    const float* neg  = (const float*)d_in[1];
    const int*   pcls = (const int*)  d_in[2];
    const int*   tcls = (const int*)  d_in[3];
    const float* Wp1  = (const float*)d_in[4];
    const float* bp1  = (const float*)d_in[5];
    const float* Wp2  = (const float*)d_in[6];
    const float* bp2  = (const float*)d_in[7];
    const float* Wu1  = (const float*)d_in[8];
    const float* bu1  = (const float*)d_in[9];
    const float* Wu2  = (const float*)d_in[10];
    const float* bu2  = (const float*)d_in[11];
    float* out = (float*)d_out;

    // dynamic smem: 14656 ull + 160 f + 32*256 int = 150,656 B
    size_t smM = (size_t)14656*8 + 160*4 + (size_t)32*256*4;

    cudaFuncSetAttribute(mega_kernel, cudaFuncAttributeMaxDynamicSharedMemorySize, (int)smM);

    gemm_all<<<512, 128>>>(pos, neg, Wp1, Wu1, pcls, tcls, out);
    mega_kernel<<<NBLK, 1024, smM>>>(bp1, Wp2, bp2, bu1, Wu2, bu2, out);
}

// round 15
// speedup vs baseline: 1.0751x; 1.0142x over previous
#include <cuda_runtime.h>

typedef unsigned long long ull;
#define ABS2 0x7FFFFFFF7FFFFFFFULL
#define NBLK 128

// ---------------- scratch (device globals; no allocations) ----------------
__device__ float g_P  [8192*128];
__device__ float g_Pb [8192*128];
__device__ float g_Q  [8192*128];
__device__ float g_Qb [8192*128];
__device__ float g_U0 [8192*128];
__device__ float g_U0b[8192*128];
__device__ float g_U1 [4096*128];
__device__ float g_U1b[4096*128];
__device__ float g_ue0[64*128];
__device__ ull   g_cand[16*512];
__device__ float g_H  [32*64*128];
__device__ float g_H2 [16*64*128];
__device__ float g_peA[32*64];
__device__ float g_ueA[32*64];
__device__ float g_peB[16*64];
__device__ float g_ueB[16*64];
__device__ int   g_subA[32*64*2];
__device__ int   g_subB[16*64*4];
__device__ ull   g_part[8];
__device__ unsigned g_done[8];
__device__ unsigned g_sync[8];

// ---------------- helpers ----------------
__device__ __forceinline__ ull pk2(float x, float y) {
    ull r; asm("mov.b64 %0, {%1,%2};" : "=l"(r) : "f"(x), "f"(y)); return r;
}
__device__ __forceinline__ void upk2(ull v, float &lo, float &hi) {
    asm("mov.b64 {%0,%1}, %2;" : "=f"(lo), "=f"(hi) : "l"(v));
}
__device__ __forceinline__ ull add2(ull a, ull b) {
    ull r; asm("add.rn.f32x2 %0, %1, %2;" : "=l"(r) : "l"(a), "l"(b)); return r;
}
__device__ __forceinline__ void fma2(ull &d, ull a, ull b) {
    asm("fma.rn.f32x2 %0, %1, %2, %0;" : "+l"(d) : "l"(a), "l"(b));
}
__device__ __forceinline__ unsigned fkey(float v) {
    unsigned b = __float_as_uint(v);
    return (b & 0x80000000u) ? ~b : (b | 0x80000000u);
}
__device__ __forceinline__ float unfkey(unsigned k) {
    unsigned b = (k & 0x80000000u) ? (k & 0x7FFFFFFFu) : ~k;
    return __uint_as_float(b);
}
__device__ __forceinline__ ull umin64(ull a, ull b) { return a < b ? a : b; }

__device__ __forceinline__ void megabar(int phase) {
    __syncthreads();
    if (threadIdx.x == 0) {
        unsigned* p = &g_sync[phase];
        asm volatile("red.release.gpu.add.u32 [%0], 1;" :: "l"(p) : "memory");
        unsigned v;
        do {
            asm volatile("ld.acquire.gpu.u32 %0, [%1];" : "=r"(v) : "l"(p) : "memory");
        } while (v < NBLK);
    }
    __syncthreads();
}

// ---------------- SGEMM: split-K=2, 64x128 tiles, 128 thr, 8x8/thread -----
// flat grid: 0..895 gemm partial tiles (tile = bid>>1, khalf = bid&1)
//            896..959 is_target (64 blocks x 128 thr)
__global__ __launch_bounds__(128) void gemm_all(
    const float* __restrict__ pos, const float* __restrict__ neg,
    const float* __restrict__ Wp1, const float* __restrict__ Wu1,
    const int* __restrict__ pcls, const int* __restrict__ tcls,
    float* __restrict__ d_out)
{
    int bid = blockIdx.x;
    int tid = threadIdx.x;

    if (bid >= 896) {    // is_target
        int i = (bid - 896)*128 + tid;
        d_out[64 + i] = (pcls[i] == tcls[i >> 10]) ? 1.f : 0.f;
        return;
    }
    if (bid == 0) {      // reset mega sync state
        if (tid < 8)  g_sync[tid] = 0u;
        if (tid >= 8 && tid < 16) { g_part[tid-8] = ~0ull; g_done[tid-8] = 0u; }
    }

    int tile = bid >> 1, kh = bid & 1;
    int kbase = kh * 128;

    const float* A; const float* W; float* C; int row0;
    if      (tile < 128) { A = pos; W = Wp1;           C = kh ? g_Pb  : g_P;  row0 = tile*64; }
    else if (tile < 256) { A = pos; W = Wp1 + 256*128; C = kh ? g_Qb  : g_Q;  row0 = (tile-128)*64; }
    else if (tile < 384) { A = pos; W = Wu1;           C = kh ? g_U0b : g_U0; row0 = (tile-256)*64; }
    else                 { A = neg; W = Wu1 + 256*128; C = kh ? g_U1b : g_U1; row0 = (tile-384)*64; }

    __shared__ float sA[2][16][68];    // transposed [k][row]
    __shared__ float sB[2][16][132];   // [k][col]

    int tx = tid & 15, ty = tid >> 4;  // tx: 8 cols, ty: 8 rows

    int aR[2], aC[2];
    #pragma unroll
    for (int i = 0; i < 2; i++) {
        int idx = tid*2 + i;           // 0..255 float4 of A tile (64x16)
        aR[i] = idx >> 2;  aC[i] = (idx & 3) * 4;
    }
    int bR[4], bC[4];
    #pragma unroll
    for (int i = 0; i < 4; i++) {
        int idx = tid*4 + i;           // 0..511 float4 of B tile (16x128)
        bR[i] = idx >> 5;  bC[i] = (idx & 31) * 4;
    }

    float4 ra[2], rb[4];
    #pragma unroll
    for (int i = 0; i < 2; i++)
        ra[i] = *(const float4*)(A + (size_t)(row0 + aR[i])*256 + kbase + aC[i]);
    #pragma unroll
    for (int i = 0; i < 4; i++)
        rb[i] = *(const float4*)(W + (size_t)(kbase + bR[i])*128 + bC[i]);

    ull acc2[8][4];
    #pragma unroll
    for (int i = 0; i < 8; i++)
        #pragma unroll
        for (int j = 0; j < 4; j++) acc2[i][j] = 0ull;

    for (int k0 = 0; k0 < 8; k0++) {
        int buf = k0 & 1;
        #pragma unroll
        for (int i = 0; i < 2; i++) {
            sA[buf][aC[i]+0][aR[i]] = ra[i].x;
            sA[buf][aC[i]+1][aR[i]] = ra[i].y;
            sA[buf][aC[i]+2][aR[i]] = ra[i].z;
            sA[buf][aC[i]+3][aR[i]] = ra[i].w;
        }
        #pragma unroll
        for (int i = 0; i < 4; i++)
            *(float4*)&sB[buf][bR[i]][bC[i]] = rb[i];
        __syncthreads();
        if (k0 < 7) {
            #pragma unroll
            for (int i = 0; i < 2; i++)
                ra[i] = *(const float4*)(A + (size_t)(row0 + aR[i])*256 + kbase + (k0+1)*16 + aC[i]);
            #pragma unroll
            for (int i = 0; i < 4; i++)
                rb[i] = *(const float4*)(W + (size_t)(kbase + (k0+1)*16 + bR[i])*128 + bC[i]);
        }
        #pragma unroll
        for (int k = 0; k < 16; k++) {
            float4 a0 = *(const float4*)&sA[buf][k][ty*8];
            float4 a1 = *(const float4*)&sA[buf][k][ty*8 + 4];
            ull bp[4];
            bp[0] = *(const ull*)&sB[buf][k][tx*8];
            bp[1] = *(const ull*)&sB[buf][k][tx*8 + 2];
            bp[2] = *(const ull*)&sB[buf][k][tx*8 + 4];
            bp[3] = *(const ull*)&sB[buf][k][tx*8 + 6];
            float av[8] = {a0.x, a0.y, a0.z, a0.w, a1.x, a1.y, a1.z, a1.w};
            #pragma unroll
            for (int i = 0; i < 8; i++) {
                ull ap = pk2(av[i], av[i]);
                #pragma unroll
                for (int j = 0; j < 4; j++) fma2(acc2[i][j], ap, bp[j]);
            }
        }
        __syncthreads();
    }
    #pragma unroll
    for (int i = 0; i < 8; i++) {
        int r = row0 + ty*8 + i;
        float c[8];
        #pragma unroll
        for (int j = 0; j < 4; j++) upk2(acc2[i][j], c[2*j], c[2*j+1]);
        *(float4*)(C + (size_t)r*128 + tx*8    ) = make_float4(c[0],c[1],c[2],c[3]);
        *(float4*)(C + (size_t)r*128 + tx*8 + 4) = make_float4(c[4],c[5],c[6],c[7]);
    }
}

// ---------------- radix threshold ----------------
template<int E, int NW>
__device__ void radix_thresh(const ull (&pk)[E], int K, int* hist,
                             unsigned &T, int &rem)
{
    __shared__ int wred[8];
    __shared__ int s_bin, s_prev, s_rem;
    __shared__ unsigned s_pref;
    int tid = threadIdx.x;
    int wid = tid >> 5, lane = tid & 31;
    if (tid == 0) { s_pref = 0u; s_rem = K; }
    __syncthreads();
    #pragma unroll
    for (int pass = 0; pass < 4; pass++) {
        int shift = 24 - 8*pass;
        for (int i = tid; i < NW*256; i += blockDim.x) hist[i] = 0;
        __syncthreads();
        unsigned pmask = pass ? (0xFFFFFFFFu << (shift + 8)) : 0u;
        unsigned pref = s_pref;
        #pragma unroll
        for (int e = 0; e < E; e++) {
            unsigned k = (unsigned)(pk[e] >> 32);
            if ((k & pmask) == pref)
                atomicAdd(&hist[wid*256 + ((k >> shift) & 255)], 1);
        }
        __syncthreads();
        int tot = 0, v = 0;
        if (tid < 256) {
            #pragma unroll
            for (int w = 0; w < NW; w++) tot += hist[w*256 + tid];
            v = tot;
            #pragma unroll
            for (int d = 1; d < 32; d <<= 1) {
                int u = __shfl_up_sync(0xffffffffu, v, d);
                if (lane >= d) v += u;
            }
            if (lane == 31) wred[wid] = v;
        }
        __syncthreads();
        if (tid == 0) {
            int acc = 0;
            #pragma unroll
            for (int w = 0; w < 8; w++) { int t = wred[w]; wred[w] = acc; acc += t; }
        }
        __syncthreads();
        if (tid < 256) {
            v += wred[wid];
            int rm = s_rem;
            if (v >= rm && (v - tot) < rm) { s_bin = tid; s_prev = v - tot; }
        }
        __syncthreads();
        if (tid == 0) { s_rem -= s_prev; s_pref = pref | ((unsigned)s_bin << shift); }
        __syncthreads();
    }
    T = s_pref;
    rem = s_rem;
}

template<int E, int NW>
__device__ void collect_packed(ull (&pk)[E], int K, unsigned T, int rem, ull* cand)
{
    __shared__ ull wmin[NW];
    __shared__ ull s_minv;
    __shared__ int s_cnt;
    int tid = threadIdx.x;
    if (tid == 0) s_cnt = 0;
    __syncthreads();
    #pragma unroll
    for (int e = 0; e < E; e++) {
        if ((unsigned)(pk[e] >> 32) < T) {
            int p = atomicAdd(&s_cnt, 1);
            cand[p] = pk[e];
        }
    }
    __syncthreads();
    int base = K - rem;
    for (int r = 0; r < rem; r++) {
        ull m = ~0ull;
        #pragma unroll
        for (int e = 0; e < E; e++)
            if ((unsigned)(pk[e] >> 32) == T) m = umin64(m, pk[e]);
        #pragma unroll
        for (int o = 16; o; o >>= 1) m = umin64(m, __shfl_down_sync(0xffffffffu, m, o));
        if ((tid & 31) == 0) wmin[tid >> 5] = m;
        __syncthreads();
        if (tid == 0) {
            ull mm = ~0ull;
            #pragma unroll
            for (int w = 0; w < NW; w++) mm = umin64(mm, wmin[w]);
            s_minv = mm;
            cand[base + r] = mm;
        }
        __syncthreads();
        ull mm = s_minv;
        #pragma unroll
        for (int e = 0; e < E; e++)
            if (pk[e] == mm) pk[e] = ~0ull;
    }
    __syncthreads();
}

// ---------------- persistent tail kernel (1024 threads) -------------------
__global__ __launch_bounds__(1024) void mega_kernel(
    const float* __restrict__ bp1, const float* __restrict__ Wp2,
    const float* __restrict__ bp2, const float* __restrict__ bu1,
    const float* __restrict__ Wu2, const float* __restrict__ bu2,
    float* __restrict__ d_out)
{
    extern __shared__ char smraw[];
    ull* smu = (ull*)smraw;
    int tid = threadIdx.x, bid = blockIdx.x;

    ull* sU1p  = smu;                    // 4160
    ull* sH0p  = smu + 4160;             // 64 x 33
    ull* sH1p  = sH0p + 2112;            // 64 x 129
    ull* sw2h  = sH1p + 8256;            // 64
    ull* candB = sw2h + 64;              // 64
    float* sb0B = (float*)(candB + 64);  // 32
    float* sb1B = sb0B + 32;             // 128
    int* histB  = (int*)(sb1B + 128);    // 32*256

    int bnB = bid >> 2, quadB = bid & 3, m0offB = quadB * 32;

    // ===== Phase A: unary energies (partials summed lo+hi) =====
    {
        __shared__ float redbuf[32];
        int b = bid >> 1;
        int mbase = (bid & 1) * 64;
        int hp = tid & 63, ms = tid >> 6;
        for (int i = tid; i < 64*64; i += 1024) {
            int n = i >> 6, p = i & 63;
            float2 v  = *(const float2*)(g_U1  + (size_t)b*64*128 + n*128 + 2*p);
            float2 vb = *(const float2*)(g_U1b + (size_t)b*64*128 + n*128 + 2*p);
            sU1p[p*65 + n] = pk2((v.x + vb.x) + bu1[2*p], (v.y + vb.y) + bu1[2*p+1]);
        }
        float w0 = Wu2[2*hp], w1 = Wu2[2*hp+1];
        float b2u = bu2[0];
        __syncthreads();
        for (int it = 0; it < 4; it++) {
            int m = mbase + it*16 + ms;
            float2 u0a = *(const float2*)(g_U0  + ((size_t)b*128 + m)*128 + 2*hp);
            float2 u0b = *(const float2*)(g_U0b + ((size_t)b*128 + m)*128 + 2*hp);
            ull up = pk2(u0a.x + u0b.x, u0a.y + u0b.y);
            ull acc = 0ull;
            #pragma unroll 8
            for (int n = 0; n < 64; n++) {
                ull s = add2(up, sU1p[hp*65 + n]);
                acc = add2(acc, add2(s, s & ABS2));
            }
            float lo, hi; upk2(acc, lo, hi);
            float v = lo*w0 + hi*w1;
            #pragma unroll
            for (int off = 16; off; off >>= 1) v += __shfl_down_sync(0xffffffffu, v, off);
            if ((tid & 31) == 0) redbuf[tid >> 5] = v;
            __syncthreads();
            if (hp == 0) g_ue0[b*128 + m] = (redbuf[2*ms] + redbuf[2*ms+1]) * (0.5f/64.f) + b2u;
            __syncthreads();
        }
    }

    // ===== preload phase-B tiles (partials summed) =====
    {
        size_t off0 = (size_t)(2*bnB  )*128*128 + (size_t)m0offB*128;
        size_t off1 = (size_t)(2*bnB+1)*128*128;
        for (int i = tid; i < 32*64; i += 1024) {
            int m = i >> 6, hp = i & 63;
            float2 v  = *(const float2*)(g_P  + off0 + m*128 + 2*hp);
            float2 vb = *(const float2*)(g_Pb + off0 + m*128 + 2*hp);
            sH0p[hp*33 + m] = pk2(v.x + vb.x, v.y + vb.y);
        }
        for (int i = tid; i < 128*64; i += 1024) {
            int m = i >> 6, hp = i & 63;
            float2 v  = *(const float2*)(g_Q  + off1 + m*128 + 2*hp);
            float2 vb = *(const float2*)(g_Qb + off1 + m*128 + 2*hp);
            sH1p[hp*129 + m] = pk2((v.x + vb.x) + bp1[2*hp], (v.y + vb.y) + bp1[2*hp+1]);
        }
        if (tid < 64) sw2h[tid] = pk2(0.5f*Wp2[2*tid], 0.5f*Wp2[2*tid+1]);
    }
    megabar(0);

    // ===== Phase B: level-0 quadrant scores + top-64 =====
    {
        float b2 = bp2[0];
        if (tid >= 64 && tid < 96)   sb0B[tid-64] = g_ue0[(2*bnB)*128 + m0offB + tid-64] - b2;
        if (tid >= 128 && tid < 256) sb1B[tid-128] = g_ue0[(2*bnB+1)*128 + tid-128];
        __syncthreads();

        int i0 = tid >> 7, jl = tid & 127;
        ull acc[4];
        #pragma unroll
        for (int c = 0; c < 4; c++) acc[c] = 0ull;
        for (int hp = 0; hp < 64; hp++) {
            ull wp = sw2h[hp];
            ull B = sH1p[hp*129 + jl];
            #pragma unroll
            for (int c = 0; c < 4; c++) {
                ull s = add2(sH0p[hp*33 + i0 + 8*c], B);
                s = add2(s, s & ABS2);
                fma2(acc[c], s, wp);
            }
        }
        ull pk[4];
        #pragma unroll
        for (int c = 0; c < 4; c++) {
            float lo, hi; upk2(acc[c], lo, hi);
            int m0 = i0 + 8*c;
            float val = sb0B[m0] + sb1B[jl] - (lo + hi);
            int gidx = (m0offB + m0) * 128 + jl;
            pk[c] = ((ull)fkey(val) << 32) | (unsigned)gidx;
        }
        unsigned T; int rem;
        radix_thresh<4,32>(pk, 64, histB, T, rem);
        collect_packed<4,32>(pk, 64, T, rem, candB);
        if (tid < 64) g_cand[(bnB*4 + quadB)*64 + tid] = candB[tid];
    }
    megabar(1);

    // ===== Phase C+D: level-0 merge (x4 redundant) + H gather =====
    {
        int bn = bid >> 2;
        ull*   scand = smu;                // 256
        int*   s_m0  = (int*)(scand + 256);// 64
        int*   s_m1  = s_m0 + 64;          // 64
        float* s_v   = (float*)(s_m1 + 64);// 64
        if (tid < 256) scand[tid] = g_cand[bn*256 + tid];
        __syncthreads();
        if (tid < 256) {
            ull c = scand[tid]; int rank = 0;
            #pragma unroll 16
            for (int i = 0; i < 256; i++) rank += (scand[i] < c) ? 1 : 0;
            if (rank < 64) {
                int j = (int)(c & 0xFFFFFFFFu);
                s_m0[rank] = j >> 7; s_m1[rank] = j & 127;
                s_v[rank] = unfkey((unsigned)(c >> 32));
            }
        }
        __syncthreads();
        if (tid < 64) {
            int m0 = s_m0[tid], m1 = s_m1[tid];
            float uen = g_ue0[(2*bn)*128 + m0] + g_ue0[(2*bn+1)*128 + m1];
            g_ueA[bn*64 + tid] = uen;
            g_peA[bn*64 + tid] = s_v[tid] - uen;
            g_subA[(bn*64 + tid)*2    ] = m0;
            g_subA[(bn*64 + tid)*2 + 1] = m1;
        }
        __syncthreads();
        if (tid < 512) {
            int r = (bid & 3)*16 + (tid >> 5), q = tid & 31;
            const float4* Xl = (const float4*)((bn & 1) ? g_Q  : g_P);
            const float4* Xh = (const float4*)((bn & 1) ? g_Qb : g_Pb);
            size_t i0x = ((size_t)(bn*2    )*128 + s_m0[r])*32 + q;
            size_t i1x = ((size_t)(bn*2 + 1)*128 + s_m1[r])*32 + q;
            float4 a = Xl[i0x], av = Xh[i0x];
            float4 b = Xl[i1x], bv = Xh[i1x];
            a.x += av.x; a.y += av.y; a.z += av.z; a.w += av.w;
            b.x += bv.x; b.y += bv.y; b.z += bv.z; b.w += bv.w;
            ((float4*)g_H)[((size_t)bn*64 + r)*32 + q] =
                make_float4((a.x+b.x)*0.5f, (a.y+b.y)*0.5f, (a.z+b.z)*0.5f, (a.w+b.w)*0.5f);
        }
    }
    megabar(2);

    // ===== Phase E: level-1 strip scores + strip top-64 (128 blocks) =====
    {
        int bn = bid >> 3, st = bid & 7, m0off = st * 8;
        ull* sH0pE  = smu;                 // 64 x 9
        ull* sH1pE  = sH0pE + 64*9;        // 64 x 65
        ull* sw2hE  = sH1pE + 64*65;       // 64
        ull* svals  = sw2hE + 64;          // 512
        float* sb0 = (float*)(svals + 512); // 8
        float* sb1 = sb0 + 8;               // 64

        const float* h0 = g_H + (size_t)(2*bn  )*64*128 + (size_t)m0off*128;
        const float* h1 = g_H + (size_t)(2*bn+1)*64*128;
        if (tid < 512) {
            int m = tid >> 6, hp = tid & 63;
            float2 v = *(const float2*)(h0 + m*128 + 2*hp);
            sH0pE[hp*9 + m] = pk2(v.x, v.y);
        }
        for (int i = tid; i < 64*64; i += 1024) {
            int m = i >> 6, hp = i & 63;
            float2 v = *(const float2*)(h1 + m*128 + 2*hp);
            sH1pE[hp*65 + m] = pk2(v.x + bp1[2*hp], v.y + bp1[2*hp+1]);
        }
        if (tid < 64) sw2hE[tid] = pk2(0.5f*Wp2[2*tid], 0.5f*Wp2[2*tid+1]);
        float b2 = bp2[0];
        if (tid >= 64 && tid < 72)
            sb0[tid-64] = g_ueA[(2*bn)*64 + m0off + tid-64]
                        + g_peA[(2*bn)*64 + m0off + tid-64] - b2;
        if (tid >= 128 && tid < 192) {
            int m = tid - 128;
            sb1[m] = g_ueA[(2*bn+1)*64 + m] + g_peA[(2*bn+1)*64 + m];
        }
        __syncthreads();

        if (tid < 512) {
            int m0l = tid >> 6, m1 = tid & 63;
            ull acc = 0ull;
            for (int hp = 0; hp < 64; hp++) {
                ull s = add2(sH0pE[hp*9 + m0l], sH1pE[hp*65 + m1]);
                s = add2(s, s & ABS2);
                fma2(acc, s, sw2hE[hp]);
            }
            float lo, hi; upk2(acc, lo, hi);
            float val = sb0[m0l] + sb1[m1] - (lo + hi);
            int gidx = (m0off + m0l) * 64 + m1;
            svals[tid] = ((ull)fkey(val) << 32) | (unsigned)gidx;
        }
        __syncthreads();
        if (tid < 512) {
            ull c = svals[tid];
            int rank = 0;
            #pragma unroll 16
            for (int i = 0; i < 512; i++) rank += (svals[i] < c) ? 1 : 0;
            if (rank < 64) g_cand[bn*512 + st*64 + rank] = c;
        }
    }
    megabar(3);

    // ===== Phase F+G: level-1 merge (x8 redundant) + H2 gather =====
    {
        int bn = bid >> 3;
        ull*   scand = smu;                 // 512
        int*   s_m0  = (int*)(scand + 512); // 64
        int*   s_m1  = s_m0 + 64;           // 64
        float* s_v   = (float*)(s_m1 + 64); // 64
        int*   s_sub = (int*)(s_v + 64);    // 256
        if (tid < 512) scand[tid] = g_cand[bn*512 + tid];
        __syncthreads();
        if (tid < 512) {
            ull c = scand[tid]; int rank = 0;
            #pragma unroll 16
            for (int i = 0; i < 512; i++) rank += (scand[i] < c) ? 1 : 0;
            if (rank < 64) {
                int j = (int)(c & 0xFFFFFFFFu);
                s_m0[rank] = j >> 6; s_m1[rank] = j & 63;
                s_v[rank] = unfkey((unsigned)(c >> 32));
            }
        }
        __syncthreads();
        if (tid < 64) {
            int m0 = s_m0[tid], m1 = s_m1[tid];
            float uen = g_ueA[(2*bn)*64 + m0] + g_ueA[(2*bn+1)*64 + m1];
            g_ueB[bn*64 + tid] = uen;
            g_peB[bn*64 + tid] = s_v[tid] - uen;
            int a0 = g_subA[((2*bn)*64 + m0)*2], a1 = g_subA[((2*bn)*64 + m0)*2 + 1];
            int b0 = g_subA[((2*bn+1)*64 + m1)*2], b1 = g_subA[((2*bn+1)*64 + m1)*2 + 1];
            s_sub[tid*4+0] = a0; s_sub[tid*4+1] = a1;
            s_sub[tid*4+2] = b0; s_sub[tid*4+3] = b1;
            g_subB[(bn*64 + tid)*4 + 0] = a0;
            g_subB[(bn*64 + tid)*4 + 1] = a1;
            g_subB[(bn*64 + tid)*4 + 2] = b0;
            g_subB[(bn*64 + tid)*4 + 3] = b1;
        }
        __syncthreads();
        if (tid < 256) {
            int r = (bid & 7)*8 + (tid >> 5), q = tid & 31;
            const float4* Xl = (const float4*)((bn & 1) ? g_Q  : g_P);
            const float4* Xh = (const float4*)((bn & 1) ? g_Qb : g_Pb);
            float4 s = make_float4(0.f, 0.f, 0.f, 0.f);
            #pragma unroll
            for (int i = 0; i < 4; i++) {
                size_t ix = ((size_t)(bn*4 + i)*128 + s_sub[r*4 + i])*32 + q;
                float4 v = Xl[ix], vb = Xh[ix];
                s.x += v.x + vb.x; s.y += v.y + vb.y;
                s.z += v.z + vb.z; s.w += v.w + vb.w;
            }
            ((float4*)g_H2)[((size_t)bn*64 + r)*32 + q] =
                make_float4(s.x*0.25f, s.y*0.25f, s.z*0.25f, s.w*0.25f);
        }
    }
    megabar(4);

    // ===== Phase H: level-2 strip argmin + fused final (32 blocks) =====
    if (bid < 32) {
        int bn = bid >> 2, m0off = (bid & 3) * 16;
        ull* sH0pH = smu;                  // 64 x 17
        ull* sH1pH = sH0pH + 64*17;        // 64 x 65
        ull* sw2hH = sH1pH + 64*65;        // 64
        float* sb0 = (float*)(sw2hH + 64); // 16
        float* sb1 = sb0 + 16;             // 64
        __shared__ ull hw[32];

        const float* h0 = g_H2 + (size_t)(2*bn  )*64*128 + (size_t)m0off*128;
        const float* h1 = g_H2 + (size_t)(2*bn+1)*64*128;
        if (tid < 16*64) {
            int m = tid >> 6, hp = tid & 63;
            float2 v = *(const float2*)(h0 + m*128 + 2*hp);
            sH0pH[hp*17 + m] = pk2(v.x, v.y);
        }
        for (int i = tid; i < 64*64; i += 1024) {
            int m = i >> 6, hp = i & 63;
            float2 v = *(const float2*)(h1 + m*128 + 2*hp);
            sH1pH[hp*65 + m] = pk2(v.x + bp1[2*hp], v.y + bp1[2*hp+1]);
        }
        if (tid < 64) sw2hH[tid] = pk2(0.5f*Wp2[2*tid], 0.5f*Wp2[2*tid+1]);
        float b2 = bp2[0];
        if (tid >= 64 && tid < 80)
            sb0[tid-64] = g_ueB[(2*bn)*64 + m0off + tid-64]
                        + g_peB[(2*bn)*64 + m0off + tid-64] - b2;
        if (tid >= 128 && tid < 192) {
            int m = tid - 128;
            sb1[m] = g_ueB[(2*bn+1)*64 + m] + g_peB[(2*bn+1)*64 + m];
        }
        __syncthreads();

        int m0l = tid >> 6, m1 = tid & 63;
        ull acc = 0ull;
        for (int hp = 0; hp < 64; hp++) {
            ull s = add2(sH0pH[hp*17 + m0l], sH1pH[hp*65 + m1]);
            s = add2(s, s & ABS2);
            fma2(acc, s, sw2hH[hp]);
        }
        ull mbest;
        {
            float lo, hi; upk2(acc, lo, hi);
            float val = sb0[m0l] + sb1[m1] - (lo + hi);
            int gidx = (m0off + m0l) * 64 + m1;
            mbest = ((ull)fkey(val) << 32) | (unsigned)gidx;
        }
        #pragma unroll
        for (int o = 16; o; o >>= 1) mbest = umin64(mbest, __shfl_down_sync(0xffffffffu, mbest, o));
        if ((tid & 31) == 0) hw[tid >> 5] = mbest;
        __syncthreads();
        if (tid == 0) {
            ull mm = ~0ull;
            #pragma unroll
            for (int w = 0; w < 32; w++) mm = umin64(mm, hw[w]);
            asm volatile("red.global.min.u64 [%0], %1;" :: "l"(&g_part[bn]), "l"(mm) : "memory");
            unsigned old;
            asm volatile("atom.acq_rel.gpu.global.add.u32 %0, [%1], %2;"
                         : "=r"(old) : "l"(&g_done[bn]), "r"(1u) : "memory");
            if (old == 3u) {
                ull fin;
                asm volatile("ld.acquire.gpu.global.u64 %0, [%1];"
                             : "=l"(fin) : "l"(&g_part[bn]) : "memory");
                int j = (int)(fin & 0xFFFFFFFFu);
                int m0 = j >> 6, m1w = j & 63;
                #pragma unroll
                for (int s = 0; s < 4; s++) {
                    d_out[bn*8 + s]     = (float)g_subB[((2*bn)*64 + m0)*4 + s];
                    d_out[bn*8 + 4 + s] = (float)g_subB[((2*bn+1)*64 + m1w)*4 + s];
                }
            }
        }
    }
}

// ---------------- launch ----------------
extern "C" void kernel_launch(void* const* d_in, const int* in_sizes, int n_in,
                              void* d_out, int out_size)
{
    const float* pos  = (const float*)d_in[0];
    const float* neg  = (const float*)d_in[1];
    const int*   pcls = (const int*)  d_in[2];
    const int*   tcls = (const int*)  d_in[3];
    const float* Wp1  = (const float*)d_in[4];
    const float* bp1  = (const float*)d_in[5];
    const float* Wp2  = (const float*)d_in[6];
    const float* bp2  = (const float*)d_in[7];
    const float* Wu1  = (const float*)d_in[8];
    const float* bu1  = (const float*)d_in[9];
    const float* Wu2  = (const float*)d_in[10];
    const float* bu2  = (const float*)d_in[11];
    float* out = (float*)d_out;

    // dynamic smem: 14656 ull + 160 f + 32*256 int = 150,656 B
    size_t smM = (size_t)14656*8 + 160*4 + (size_t)32*256*4;

    cudaFuncSetAttribute(mega_kernel, cudaFuncAttributeMaxDynamicSharedMemorySize, (int)smM);

    gemm_all<<<960, 128>>>(pos, neg, Wp1, Wu1, pcls, tcls, out);
    mega_kernel<<<NBLK, 1024, smM>>>(bp1, Wp2, bp2, bu1, Wu2, bu2, out);
}

// round 17
// speedup vs baseline: 1.1545x; 1.0739x over previous
#include <cuda_runtime.h>

typedef unsigned long long ull;
#define ABS2 0x7FFFFFFF7FFFFFFFULL

// ---------------- scratch (device globals; no allocations) ----------------
__device__ float g_P [8192*128];
__device__ float g_Q [8192*128];
__device__ float g_U0[8192*128];
__device__ float g_U1[4096*128];
__device__ float g_ue0[64*128];
__device__ ull   g_cand[16*512];
__device__ float g_H  [32*64*128];
__device__ float g_H2 [16*64*128];
__device__ float g_peA[32*64];
__device__ float g_ueA[32*64];
__device__ float g_peB[16*64];
__device__ float g_ueB[16*64];
__device__ int   g_subA[32*64*2];
__device__ int   g_subB[16*64*4];
__device__ ull   g_part[8];
__device__ unsigned g_done[8];
__device__ unsigned g_gsync[5*32];

// ---------------- helpers ----------------
__device__ __forceinline__ ull pk2(float x, float y) {
    ull r; asm("mov.b64 %0, {%1,%2};" : "=l"(r) : "f"(x), "f"(y)); return r;
}
__device__ __forceinline__ void upk2(ull v, float &lo, float &hi) {
    asm("mov.b64 {%0,%1}, %2;" : "=f"(lo), "=f"(hi) : "l"(v));
}
__device__ __forceinline__ ull add2(ull a, ull b) {
    ull r; asm("add.rn.f32x2 %0, %1, %2;" : "=l"(r) : "l"(a), "l"(b)); return r;
}
__device__ __forceinline__ void fma2(ull &d, ull a, ull b) {
    asm("fma.rn.f32x2 %0, %1, %2, %0;" : "+l"(d) : "l"(a), "l"(b));
}
__device__ __forceinline__ unsigned fkey(float v) {
    unsigned b = __float_as_uint(v);
    return (b & 0x80000000u) ? ~b : (b | 0x80000000u);
}
__device__ __forceinline__ float unfkey(unsigned k) {
    unsigned b = (k & 0x80000000u) ? (k & 0x7FFFFFFFu) : ~k;
    return __uint_as_float(b);
}
__device__ __forceinline__ ull umin64(ull a, ull b) { return a < b ? a : b; }

// dependency-exact group barrier: only the gsz blocks sharing gid synchronize
__device__ __forceinline__ void groupbar(int ph, int gid, int gsz) {
    __syncthreads();
    if (threadIdx.x == 0) {
        unsigned* p = &g_gsync[ph*32 + gid];
        asm volatile("red.release.gpu.add.u32 [%0], 1;" :: "l"(p) : "memory");
        unsigned v;
        do {
            asm volatile("ld.acquire.gpu.u32 %0, [%1];" : "=r"(v) : "l"(p) : "memory");
        } while (v < (unsigned)gsz);
    }
    __syncthreads();
}

// ---------------- SGEMM: 64x128 tiles, 128 thr, 8x8/thread (R11 version) --
__global__ __launch_bounds__(128) void gemm_all(
    const float* __restrict__ pos, const float* __restrict__ neg,
    const float* __restrict__ Wp1, const float* __restrict__ Wu1,
    const int* __restrict__ pcls, const int* __restrict__ tcls,
    float* __restrict__ d_out)
{
    int bid = blockIdx.x;
    int tid = threadIdx.x;

    if (bid >= 448) {    // is_target
        int i = (bid - 448)*128 + tid;
        d_out[64 + i] = (pcls[i] == tcls[i >> 10]) ? 1.f : 0.f;
        return;
    }
    if (bid == 0) {      // reset mega sync state (128 threads -> strided)
        for (int i = tid; i < 160; i += 128) g_gsync[i] = 0u;
        if (tid < 8) { g_part[tid] = ~0ull; g_done[tid] = 0u; }
    }

    const float* A; const float* W; float* C; int row0;
    if      (bid < 128) { A = pos; W = Wp1;           C = g_P;  row0 = bid*64; }
    else if (bid < 256) { A = pos; W = Wp1 + 256*128; C = g_Q;  row0 = (bid-128)*64; }
    else if (bid < 384) { A = pos; W = Wu1;           C = g_U0; row0 = (bid-256)*64; }
    else                { A = neg; W = Wu1 + 256*128; C = g_U1; row0 = (bid-384)*64; }

    __shared__ float sA[2][16][68];
    __shared__ float sB[2][16][132];

    int tx = tid & 15, ty = tid >> 4;

    int aR[2], aC[2];
    #pragma unroll
    for (int i = 0; i < 2; i++) {
        int idx = tid*2 + i;
        aR[i] = idx >> 2;  aC[i] = (idx & 3) * 4;
    }
    int bR[4], bC[4];
    #pragma unroll
    for (int i = 0; i < 4; i++) {
        int idx = tid*4 + i;
        bR[i] = idx >> 5;  bC[i] = (idx & 31) * 4;
    }

    float4 ra[2], rb[4];
    #pragma unroll
    for (int i = 0; i < 2; i++)
        ra[i] = *(const float4*)(A + (size_t)(row0 + aR[i])*256 + aC[i]);
    #pragma unroll
    for (int i = 0; i < 4; i++)
        rb[i] = *(const float4*)(W + (size_t)bR[i]*128 + bC[i]);

    ull acc2[8][4];
    #pragma unroll
    for (int i = 0; i < 8; i++)
        #pragma unroll
        for (int j = 0; j < 4; j++) acc2[i][j] = 0ull;

    for (int k0 = 0; k0 < 16; k0++) {
        int buf = k0 & 1;
        #pragma unroll
        for (int i = 0; i < 2; i++) {
            sA[buf][aC[i]+0][aR[i]] = ra[i].x;
            sA[buf][aC[i]+1][aR[i]] = ra[i].y;
            sA[buf][aC[i]+2][aR[i]] = ra[i].z;
            sA[buf][aC[i]+3][aR[i]] = ra[i].w;
        }
        #pragma unroll
        for (int i = 0; i < 4; i++)
            *(float4*)&sB[buf][bR[i]][bC[i]] = rb[i];
        __syncthreads();
        if (k0 < 15) {
            #pragma unroll
            for (int i = 0; i < 2; i++)
                ra[i] = *(const float4*)(A + (size_t)(row0 + aR[i])*256 + (k0+1)*16 + aC[i]);
            #pragma unroll
            for (int i = 0; i < 4; i++)
                rb[i] = *(const float4*)(W + (size_t)((k0+1)*16 + bR[i])*128 + bC[i]);
        }
        #pragma unroll
        for (int k = 0; k < 16; k++) {
            float4 a0 = *(const float4*)&sA[buf][k][ty*8];
            float4 a1 = *(const float4*)&sA[buf][k][ty*8 + 4];
            ull bp[4];
            bp[0] = *(const ull*)&sB[buf][k][tx*8];
            bp[1] = *(const ull*)&sB[buf][k][tx*8 + 2];
            bp[2] = *(const ull*)&sB[buf][k][tx*8 + 4];
            bp[3] = *(const ull*)&sB[buf][k][tx*8 + 6];
            float av[8] = {a0.x, a0.y, a0.z, a0.w, a1.x, a1.y, a1.z, a1.w};
            #pragma unroll
            for (int i = 0; i < 8; i++) {
                ull ap = pk2(av[i], av[i]);
                #pragma unroll
                for (int j = 0; j < 4; j++) fma2(acc2[i][j], ap, bp[j]);
            }
        }
        __syncthreads();
    }
    #pragma unroll
    for (int i = 0; i < 8; i++) {
        int r = row0 + ty*8 + i;
        float c[8];
        #pragma unroll
        for (int j = 0; j < 4; j++) upk2(acc2[i][j], c[2*j], c[2*j+1]);
        *(float4*)(C + (size_t)r*128 + tx*8    ) = make_float4(c[0],c[1],c[2],c[3]);
        *(float4*)(C + (size_t)r*128 + tx*8 + 4) = make_float4(c[4],c[5],c[6],c[7]);
    }
}

// ---------------- radix threshold ----------------
template<int E, int NW>
__device__ void radix_thresh(const ull (&pk)[E], int K, int* hist,
                             unsigned &T, int &rem)
{
    __shared__ int wred[8];
    __shared__ int s_bin, s_prev, s_rem;
    __shared__ unsigned s_pref;
    int tid = threadIdx.x;
    int wid = tid >> 5, lane = tid & 31;
    if (tid == 0) { s_pref = 0u; s_rem = K; }
    __syncthreads();
    #pragma unroll
    for (int pass = 0; pass < 4; pass++) {
        int shift = 24 - 8*pass;
        for (int i = tid; i < NW*256; i += blockDim.x) hist[i] = 0;
        __syncthreads();
        unsigned pmask = pass ? (0xFFFFFFFFu << (shift + 8)) : 0u;
        unsigned pref = s_pref;
        #pragma unroll
        for (int e = 0; e < E; e++) {
            unsigned k = (unsigned)(pk[e] >> 32);
            if ((k & pmask) == pref)
                atomicAdd(&hist[wid*256 + ((k >> shift) & 255)], 1);
        }
        __syncthreads();
        int tot = 0, v = 0;
        if (tid < 256) {
            #pragma unroll
            for (int w = 0; w < NW; w++) tot += hist[w*256 + tid];
            v = tot;
            #pragma unroll
            for (int d = 1; d < 32; d <<= 1) {
                int u = __shfl_up_sync(0xffffffffu, v, d);
                if (lane >= d) v += u;
            }
            if (lane == 31) wred[wid] = v;
        }
        __syncthreads();
        if (tid == 0) {
            int acc = 0;
            #pragma unroll
            for (int w = 0; w < 8; w++) { int t = wred[w]; wred[w] = acc; acc += t; }
        }
        __syncthreads();
        if (tid < 256) {
            v += wred[wid];
            int rm = s_rem;
            if (v >= rm && (v - tot) < rm) { s_bin = tid; s_prev = v - tot; }
        }
        __syncthreads();
        if (tid == 0) { s_rem -= s_prev; s_pref = pref | ((unsigned)s_bin << shift); }
        __syncthreads();
    }
    T = s_pref;
    rem = s_rem;
}

template<int E, int NW>
__device__ void collect_packed(ull (&pk)[E], int K, unsigned T, int rem, ull* cand)
{
    __shared__ ull wmin[NW];
    __shared__ ull s_minv;
    __shared__ int s_cnt;
    int tid = threadIdx.x;
    if (tid == 0) s_cnt = 0;
    __syncthreads();
    #pragma unroll
    for (int e = 0; e < E; e++) {
        if ((unsigned)(pk[e] >> 32) < T) {
            int p = atomicAdd(&s_cnt, 1);
            cand[p] = pk[e];
        }
    }
    __syncthreads();
    int base = K - rem;
    for (int r = 0; r < rem; r++) {
        ull m = ~0ull;
        #pragma unroll
        for (int e = 0; e < E; e++)
            if ((unsigned)(pk[e] >> 32) == T) m = umin64(m, pk[e]);
        #pragma unroll
        for (int o = 16; o; o >>= 1) m = umin64(m, __shfl_down_sync(0xffffffffu, m, o));
        if ((tid & 31) == 0) wmin[tid >> 5] = m;
        __syncthreads();
        if (tid == 0) {
            ull mm = ~0ull;
            #pragma unroll
            for (int w = 0; w < NW; w++) mm = umin64(mm, wmin[w]);
            s_minv = mm;
            cand[base + r] = mm;
        }
        __syncthreads();
        ull mm = s_minv;
        #pragma unroll
        for (int e = 0; e < E; e++)
            if (pk[e] == mm) pk[e] = ~0ull;
    }
    __syncthreads();
}

// ---------------- persistent tail kernel (1024 threads, group barriers) ---
__global__ __launch_bounds__(1024) void mega_kernel(
    const float* __restrict__ bp1, const float* __restrict__ Wp2,
    const float* __restrict__ bp2, const float* __restrict__ bu1,
    const float* __restrict__ Wu2, const float* __restrict__ bu2,
    float* __restrict__ d_out)
{
    extern __shared__ char smraw[];
    ull* smu = (ull*)smraw;
    int tid = threadIdx.x, bid = blockIdx.x;

    ull* sU1p  = smu;                    // 4160
    ull* sH0p  = smu + 4160;             // 64 x 33
    ull* sH1p  = sH0p + 2112;            // 64 x 129
    ull* sw2h  = sH1p + 8256;            // 64
    ull* candB = sw2h + 64;              // 64
    float* sb0B = (float*)(candB + 64);  // 32
    float* sb1B = sb0B + 32;             // 128
    int* histB  = (int*)(sb1B + 128);    // 32*256

    int bnB = bid >> 2, quadB = bid & 3, m0offB = quadB * 32;

    // ===== Phase A: unary energies (blocks 2b, 2b+1 per batch b) =====
    {
        __shared__ float redbuf[32];
        int b = bid >> 1;
        int mbase = (bid & 1) * 64;
        int hp = tid & 63, ms = tid >> 6;
        for (int i = tid; i < 64*64; i += 1024) {
            int n = i >> 6, p = i & 63;
            float2 v = *(const float2*)(g_U1 + (size_t)b*64*128 + n*128 + 2*p);
            sU1p[p*65 + n] = pk2(v.x + bu1[2*p], v.y + bu1[2*p+1]);
        }
        float w0 = Wu2[2*hp], w1 = Wu2[2*hp+1];
        float b2u = bu2[0];
        __syncthreads();
        for (int it = 0; it < 4; it++) {
            int m = mbase + it*16 + ms;
            float2 u0 = *(const float2*)(g_U0 + ((size_t)b*128 + m)*128 + 2*hp);
            ull up = pk2(u0.x, u0.y);
            ull acc = 0ull;
            #pragma unroll 8
            for (int n = 0; n < 64; n++) {
                ull s = add2(up, sU1p[hp*65 + n]);
                acc = add2(acc, add2(s, s & ABS2));
            }
            float lo, hi; upk2(acc, lo, hi);
            float v = lo*w0 + hi*w1;
            #pragma unroll
            for (int off = 16; off; off >>= 1) v += __shfl_down_sync(0xffffffffu, v, off);
            if ((tid & 31) == 0) redbuf[tid >> 5] = v;
            __syncthreads();
            if (hp == 0) g_ue0[b*128 + m] = (redbuf[2*ms] + redbuf[2*ms+1]) * (0.5f/64.f) + b2u;
            __syncthreads();
        }
    }

    // ===== preload phase-B tiles (overlaps group wait) =====
    {
        const float* h0 = g_P + (size_t)(2*bnB  )*128*128 + (size_t)m0offB*128;
        const float* h1 = g_Q + (size_t)(2*bnB+1)*128*128;
        for (int i = tid; i < 32*64; i += 1024) {
            int m = i >> 6, hp = i & 63;
            float2 v = *(const float2*)(h0 + m*128 + 2*hp);
            sH0p[hp*33 + m] = pk2(v.x, v.y);
        }
        for (int i = tid; i < 128*64; i += 1024) {
            int m = i >> 6, hp = i & 63;
            float2 v = *(const float2*)(h1 + m*128 + 2*hp);
            sH1p[hp*129 + m] = pk2(v.x + bp1[2*hp], v.y + bp1[2*hp+1]);
        }
        if (tid < 64) sw2h[tid] = pk2(0.5f*Wp2[2*tid], 0.5f*Wp2[2*tid+1]);
    }
    groupbar(0, bid >> 2, 4);   // phase B needs ue0 of batches 2bnB,2bnB+1

    // ===== Phase B: level-0 quadrant scores + top-64 =====
    {
        float b2 = bp2[0];
        if (tid >= 64 && tid < 96)   sb0B[tid-64] = g_ue0[(2*bnB)*128 + m0offB + tid-64] - b2;
        if (tid >= 128 && tid < 256) sb1B[tid-128] = g_ue0[(2*bnB+1)*128 + tid-128];
        __syncthreads();

        int i0 = tid >> 7, jl = tid & 127;
        ull acc[4];
        #pragma unroll
        for (int c = 0; c < 4; c++) acc[c] = 0ull;
        for (int hp = 0; hp < 64; hp++) {
            ull wp = sw2h[hp];
            ull B = sH1p[hp*129 + jl];
            #pragma unroll
            for (int c = 0; c < 4; c++) {
                ull s = add2(sH0p[hp*33 + i0 + 8*c], B);
                s = add2(s, s & ABS2);
                fma2(acc[c], s, wp);
            }
        }
        ull pk[4];
        #pragma unroll
        for (int c = 0; c < 4; c++) {
            float lo, hi; upk2(acc[c], lo, hi);
            int m0 = i0 + 8*c;
            float val = sb0B[m0] + sb1B[jl] - (lo + hi);
            int gidx = (m0offB + m0) * 128 + jl;
            pk[c] = ((ull)fkey(val) << 32) | (unsigned)gidx;
        }
        unsigned T; int rem;
        radix_thresh<4,32>(pk, 64, histB, T, rem);
        collect_packed<4,32>(pk, 64, T, rem, candB);
        if (tid < 64) g_cand[(bnB*4 + quadB)*64 + tid] = candB[tid];
    }
    groupbar(1, bid >> 2, 4);   // merge needs all 4 quadrant cands of bnB

    // ===== Phase C+D: level-0 merge (x4 redundant) + H gather =====
    {
        int bn = bid >> 2;
        ull*   scand = smu;                // 256
        int*   s_m0  = (int*)(scand + 256);// 64
        int*   s_m1  = s_m0 + 64;          // 64
        float* s_v   = (float*)(s_m1 + 64);// 64
        if (tid < 256) scand[tid] = g_cand[bn*256 + tid];
        __syncthreads();
        if (tid < 256) {
            ull c = scand[tid]; int rank = 0;
            #pragma unroll 16
            for (int i = 0; i < 256; i++) rank += (scand[i] < c) ? 1 : 0;
            if (rank < 64) {
                int j = (int)(c & 0xFFFFFFFFu);
                s_m0[rank] = j >> 7; s_m1[rank] = j & 127;
                s_v[rank] = unfkey((unsigned)(c >> 32));
            }
        }
        __syncthreads();
        if (tid < 64) {
            int m0 = s_m0[tid], m1 = s_m1[tid];
            float uen = g_ue0[(2*bn)*128 + m0] + g_ue0[(2*bn+1)*128 + m1];
            g_ueA[bn*64 + tid] = uen;
            g_peA[bn*64 + tid] = s_v[tid] - uen;
            g_subA[(bn*64 + tid)*2    ] = m0;
            g_subA[(bn*64 + tid)*2 + 1] = m1;
        }
        __syncthreads();
        if (tid < 512) {
            int r = (bid & 3)*16 + (tid >> 5), q = tid & 31;
            const float4* X = (const float4*)((bn & 1) ? g_Q : g_P);
            float4 a = X[((size_t)(bn*2    )*128 + s_m0[r])*32 + q];
            float4 b = X[((size_t)(bn*2 + 1)*128 + s_m1[r])*32 + q];
            ((float4*)g_H)[((size_t)bn*64 + r)*32 + q] =
                make_float4((a.x+b.x)*0.5f, (a.y+b.y)*0.5f, (a.z+b.z)*0.5f, (a.w+b.w)*0.5f);
        }
    }
    groupbar(2, bid >> 3, 8);   // phase E needs H rows of 2bnE,2bnE+1

    // ===== Phase E: level-1 strip scores + strip top-64 (128 blocks) =====
    {
        int bn = bid >> 3, st = bid & 7, m0off = st * 8;
        ull* sH0pE  = smu;                 // 64 x 9
        ull* sH1pE  = sH0pE + 64*9;        // 64 x 65
        ull* sw2hE  = sH1pE + 64*65;       // 64
        ull* svals  = sw2hE + 64;          // 512
        float* sb0 = (float*)(svals + 512); // 8
        float* sb1 = sb0 + 8;               // 64

        const float* h0 = g_H + (size_t)(2*bn  )*64*128 + (size_t)m0off*128;
        const float* h1 = g_H + (size_t)(2*bn+1)*64*128;
        if (tid < 512) {
            int m = tid >> 6, hp = tid & 63;
            float2 v = *(const float2*)(h0 + m*128 + 2*hp);
            sH0pE[hp*9 + m] = pk2(v.x, v.y);
        }
        for (int i = tid; i < 64*64; i += 1024) {
            int m = i >> 6, hp = i & 63;
            float2 v = *(const float2*)(h1 + m*128 + 2*hp);
            sH1pE[hp*65 + m] = pk2(v.x + bp1[2*hp], v.y + bp1[2*hp+1]);
        }
        if (tid < 64) sw2hE[tid] = pk2(0.5f*Wp2[2*tid], 0.5f*Wp2[2*tid+1]);
        float b2 = bp2[0];
        if (tid >= 64 && tid < 72)
            sb0[tid-64] = g_ueA[(2*bn)*64 + m0off + tid-64]
                        + g_peA[(2*bn)*64 + m0off + tid-64] - b2;
        if (tid >= 128 && tid < 192) {
            int m = tid - 128;
            sb1[m] = g_ueA[(2*bn+1)*64 + m] + g_peA[(2*bn+1)*64 + m];
        }
        __syncthreads();

        if (tid < 512) {
            int m0l = tid >> 6, m1 = tid & 63;
            ull acc = 0ull;
            for (int hp = 0; hp < 64; hp++) {
                ull s = add2(sH0pE[hp*9 + m0l], sH1pE[hp*65 + m1]);
                s = add2(s, s & ABS2);
                fma2(acc, s, sw2hE[hp]);
            }
            float lo, hi; upk2(acc, lo, hi);
            float val = sb0[m0l] + sb1[m1] - (lo + hi);
            int gidx = (m0off + m0l) * 64 + m1;
            svals[tid] = ((ull)fkey(val) << 32) | (unsigned)gidx;
        }
        __syncthreads();
        if (tid < 512) {
            ull c = svals[tid];
            int rank = 0;
            #pragma unroll 16
            for (int i = 0; i < 512; i++) rank += (svals[i] < c) ? 1 : 0;
            if (rank < 64) g_cand[bn*512 + st*64 + rank] = c;
        }
    }
    groupbar(3, bid >> 3, 8);   // merge needs all 8 strip cands of bn

    // ===== Phase F+G: level-1 merge (x8 redundant) + H2 gather =====
    {
        int bn = bid >> 3;
        ull*   scand = smu;                 // 512
        int*   s_m0  = (int*)(scand + 512); // 64
        int*   s_m1  = s_m0 + 64;           // 64
        float* s_v   = (float*)(s_m1 + 64); // 64
        int*   s_sub = (int*)(s_v + 64);    // 256
        if (tid < 512) scand[tid] = g_cand[bn*512 + tid];
        __syncthreads();
        if (tid < 512) {
            ull c = scand[tid]; int rank = 0;
            #pragma unroll 16
            for (int i = 0; i < 512; i++) rank += (scand[i] < c) ? 1 : 0;
            if (rank < 64) {
                int j = (int)(c & 0xFFFFFFFFu);
                s_m0[rank] = j >> 6; s_m1[rank] = j & 63;
                s_v[rank] = unfkey((unsigned)(c >> 32));
            }
        }
        __syncthreads();
        if (tid < 64) {
            int m0 = s_m0[tid], m1 = s_m1[tid];
            float uen = g_ueA[(2*bn)*64 + m0] + g_ueA[(2*bn+1)*64 + m1];
            g_ueB[bn*64 + tid] = uen;
            g_peB[bn*64 + tid] = s_v[tid] - uen;
            int a0 = g_subA[((2*bn)*64 + m0)*2], a1 = g_subA[((2*bn)*64 + m0)*2 + 1];
            int b0 = g_subA[((2*bn+1)*64 + m1)*2], b1 = g_subA[((2*bn+1)*64 + m1)*2 + 1];
            s_sub[tid*4+0] = a0; s_sub[tid*4+1] = a1;
            s_sub[tid*4+2] = b0; s_sub[tid*4+3] = b1;
            g_subB[(bn*64 + tid)*4 + 0] = a0;
            g_subB[(bn*64 + tid)*4 + 1] = a1;
            g_subB[(bn*64 + tid)*4 + 2] = b0;
            g_subB[(bn*64 + tid)*4 + 3] = b1;
        }
        __syncthreads();
        if (tid < 256) {
            int r = (bid & 7)*8 + (tid >> 5), q = tid & 31;
            const float4* X = (const float4*)((bn & 1) ? g_Q : g_P);
            float4 s = make_float4(0.f, 0.f, 0.f, 0.f);
            #pragma unroll
            for (int i = 0; i < 4; i++) {
                float4 v = X[((size_t)(bn*4 + i)*128 + s_sub[r*4 + i])*32 + q];
                s.x += v.x; s.y += v.y; s.z += v.z; s.w += v.w;
            }
            ((float4*)g_H2)[((size_t)bn*64 + r)*32 + q] =
                make_float4(s.x*0.25f, s.y*0.25f, s.z*0.25f, s.w*0.25f);
        }
    }
    groupbar(4, bid >> 4, 16);  // phase H needs H2 of 2bnH,2bnH+1

    // ===== Phase H: level-2 strip argmin + fused final (128 blocks) =====
    {
        int bn = bid >> 4, m0off = (bid & 15) * 4;
        ull* sH0pH = smu;                  // 4 x 17 rows used
        ull* sH1pH = sH0pH + 64*17;        // 64 x 65
        ull* sw2hH = sH1pH + 64*65;        // 64
        float* sb0 = (float*)(sw2hH + 64); // 4
        float* sb1 = sb0 + 4;              // 64
        __shared__ ull hw[8];

        const float* h0 = g_H2 + (size_t)(2*bn  )*64*128 + (size_t)m0off*128;
        const float* h1 = g_H2 + (size_t)(2*bn+1)*64*128;
        if (tid < 4*64) {
            int m = tid >> 6, hp = tid & 63;
            float2 v = *(const float2*)(h0 + m*128 + 2*hp);
            sH0pH[hp*17 + m] = pk2(v.x, v.y);
        }
        for (int i = tid; i < 64*64; i += 1024) {
            int m = i >> 6, hp = i & 63;
            float2 v = *(const float2*)(h1 + m*128 + 2*hp);
            sH1pH[hp*65 + m] = pk2(v.x + bp1[2*hp], v.y + bp1[2*hp+1]);
        }
        if (tid < 64) sw2hH[tid] = pk2(0.5f*Wp2[2*tid], 0.5f*Wp2[2*tid+1]);
        float b2 = bp2[0];
        if (tid >= 64 && tid < 68)
            sb0[tid-64] = g_ueB[(2*bn)*64 + m0off + tid-64]
                        + g_peB[(2*bn)*64 + m0off + tid-64] - b2;
        if (tid >= 128 && tid < 192) {
            int m = tid - 128;
            sb1[m] = g_ueB[(2*bn+1)*64 + m] + g_peB[(2*bn+1)*64 + m];
        }
        __syncthreads();

        ull mbest = ~0ull;
        if (tid < 256) {
            int m0l = tid >> 6, m1 = tid & 63;
            ull acc = 0ull;
            for (int hp = 0; hp < 64; hp++) {
                ull s = add2(sH0pH[hp*17 + m0l], sH1pH[hp*65 + m1]);
                s = add2(s, s & ABS2);
                fma2(acc, s, sw2hH[hp]);
            }
            float lo, hi; upk2(acc, lo, hi);
            float val = sb0[m0l] + sb1[m1] - (lo + hi);
            int gidx = (m0off + m0l) * 64 + m1;
            mbest = ((ull)fkey(val) << 32) | (unsigned)gidx;
        }
        #pragma unroll
        for (int o = 16; o; o >>= 1) mbest = umin64(mbest, __shfl_down_sync(0xffffffffu, mbest, o));
        if (tid < 256 && (tid & 31) == 0) hw[tid >> 5] = mbest;
        __syncthreads();
        if (tid == 0) {
            ull mm = ~0ull;
            #pragma unroll
            for (int w = 0; w < 8; w++) mm = umin64(mm, hw[w]);
            asm volatile("red.global.min.u64 [%0], %1;" :: "l"(&g_part[bn]), "l"(mm) : "memory");
            unsigned old;
            asm volatile("atom.acq_rel.gpu.global.add.u32 %0, [%1], %2;"
                         : "=r"(old) : "l"(&g_done[bn]), "r"(1u) : "memory");
            if (old == 15u) {
                ull fin;
                asm volatile("ld.acquire.gpu.global.u64 %0, [%1];"
                             : "=l"(fin) : "l"(&g_part[bn]) : "memory");
                int j = (int)(fin & 0xFFFFFFFFu);
                int m0 = j >> 6, m1w = j & 63;
                #pragma unroll
                for (int s = 0; s < 4; s++) {
                    d_out[bn*8 + s]     = (float)g_subB[((2*bn)*64 + m0)*4 + s];
                    d_out[bn*8 + 4 + s] = (float)g_subB[((2*bn+1)*64 + m1w)*4 + s];
                }
            }
        }
    }
}

// ---------------- launch ----------------
extern "C" void kernel_launch(void* const* d_in, const int* in_sizes, int n_in,
                              void* d_out, int out_size)
{
    const float* pos  = (const float*)d_in[0];
    const float* neg  = (const float*)d_in[1];
    const int*   pcls = (const int*)  d_in[2];
    const int*   tcls = (const int*)  d_in[3];
    const float* Wp1  = (const float*)d_in[4];
    const float* bp1  = (const float*)d_in[5];
    const float* Wp2  = (const float*)d_in[6];
    const float* bp2  = (const float*)d_in[7];
    const float* Wu1  = (const float*)d_in[8];
    const float* bu1  = (const float*)d_in[9];
    const float* Wu2  = (const float*)d_in[10];
    const float* bu2  = (const float*)d_in[11];
    float* out = (float*)d_out;

    // dynamic smem: 14656 ull + 160 f + 32*256 int = 150,656 B
    size_t smM = (size_t)14656*8 + 160*4 + (size_t)32*256*4;

    cudaFuncSetAttribute(mega_kernel, cudaFuncAttributeMaxDynamicSharedMemorySize, (int)smM);

    gemm_all<<<512, 128>>>(pos, neg, Wp1, Wu1, pcls, tcls, out);
    mega_kernel<<<128, 1024, smM>>>(bp1, Wp2, bp2, bu1, Wu2, bu2, out);
}